// round 15
// baseline (speedup 1.0000x reference)
#include <cuda_runtime.h>
#include <cuda_fp16.h>
#include <math.h>
#include <stdint.h>

// ---------------- problem constants ----------------
#define T_TOK 4096
#define HID   2048
#define SEQ   1024
#define BATCH 4
#define NHEAD 32
#define NKVH  4
#define HDIM  128
#define NEXP  32
#define TOPK  8
#define EI    768
#define SI    4096
#define GQA   8
#define EPSV  1e-6f
#define QKVN  (NHEAD*HDIM + 2*NKVH*HDIM)   // 5120
#define NPAIR (T_TOK*TOPK)

// ---------------- scratch (fp32) ----------------
__device__ float g_xn  [T_TOK*HID];
__device__ float g_h   [T_TOK*HID];
__device__ float g_cos[SEQ*(HDIM/2)];
__device__ float g_sin[SEQ*(HDIM/2)];
__device__ int   g_topi[NPAIR];
__device__ float g_topw[NPAIR];
__device__ int   g_cnt[NEXP];
__device__ int   g_off[NEXP+1];
__device__ int   g_cur[NEXP];
__device__ int   g_ptok[NPAIR];
__device__ int   g_ppos[NPAIR];
__device__ float g_sig[T_TOK];
// ---------------- scratch (fp16) ----------------
__device__ __half g_qkvh [(long)T_TOK*QKVN];
__device__ __half g_xh   [T_TOK*HID];
__device__ __half g_atth [T_TOK*NHEAD*HDIM];
__device__ __half g_guh  [(long)NPAIR*2*EI];
__device__ __half g_acth [(long)NPAIR*EI];
__device__ __half g_downh[(long)NPAIR*HID];
__device__ __half g_gsh  [(long)T_TOK*2*SI];
__device__ __half g_shh  [T_TOK*SI];
// fp16 transposed weights [N][K]
__device__ __half g_Wqkv[QKVN*HID];
__device__ __half g_WoT [HID*NHEAD*HDIM];
__device__ __half g_WguT[(long)NEXP*2*EI*HID];
__device__ __half g_WedT[(long)NEXP*HID*EI];
__device__ __half g_WsguT[(long)2*SI*HID];
__device__ __half g_WsdT[HID*SI];

// ---------------- helpers ----------------
__device__ __forceinline__ uint32_t smem_u32(const void* p){
    uint32_t a;
    asm("{ .reg .u64 t; cvta.to.shared.u64 t, %1; cvt.u32.u64 %0, t; }" : "=r"(a) : "l"(p));
    return a;
}
__device__ __forceinline__ void cp_async16(uint32_t saddr, const void* gaddr, uint32_t sz){
    asm volatile("cp.async.cg.shared.global [%0], [%1], 16, %2;"
        :: "r"(saddr), "l"(gaddr), "r"(sz) : "memory");
}
__device__ __forceinline__ void cp_commit(){
    asm volatile("cp.async.commit_group;" ::: "memory");
}
template<int N>
__device__ __forceinline__ void cp_wait(){
    asm volatile("cp.async.wait_group %0;" :: "n"(N) : "memory");
}
__device__ __forceinline__ void mma_f16(float* c, uint32_t a0, uint32_t a1, uint32_t a2, uint32_t a3,
                                        uint32_t b0, uint32_t b1)
{
    asm volatile("mma.sync.aligned.m16n8k16.row.col.f32.f16.f16.f32 "
        "{%0,%1,%2,%3}, {%4,%5,%6,%7}, {%8,%9}, {%0,%1,%2,%3};"
        : "+f"(c[0]), "+f"(c[1]), "+f"(c[2]), "+f"(c[3])
        : "r"(a0), "r"(a1), "r"(a2), "r"(a3), "r"(b0), "r"(b1));
}
#define LDSM_X4(r0, r1, r2, r3, addr) \
    asm volatile("ldmatrix.sync.aligned.m8n8.x4.shared.b16 {%0,%1,%2,%3}, [%4];" \
        : "=r"(r0), "=r"(r1), "=r"(r2), "=r"(r3) : "r"(addr))
#define LDSM_X4_T(r0, r1, r2, r3, addr) \
    asm volatile("ldmatrix.sync.aligned.m8n8.x4.trans.shared.b16 {%0,%1,%2,%3}, [%4];" \
        : "=r"(r0), "=r"(r1), "=r"(r2), "=r"(r3) : "r"(addr))
__device__ __forceinline__ uint32_t packh2(float a, float b){
    __half2 h = __floats2half2_rn(a, b);
    return *reinterpret_cast<uint32_t*>(&h);
}

// ---------------- weight transpose + fp16 convert: src[K][N] -> dst[N][K], 64x64 tiles ----------------
__global__ void tcvt_k(const float* __restrict__ src, __half* __restrict__ dst, int K, int N,
                       long srcZ, long dstZ)
{
    __shared__ float t[64][65];
    long z = blockIdx.z;
    src += z * srcZ;
    dst += z * dstZ;
    int n0 = blockIdx.x*64, k0 = blockIdx.y*64;
    int tx = threadIdx.x, ty = threadIdx.y;   // (32, 8)
#pragma unroll
    for (int i = 0; i < 8; i++) {
        int kr = ty + i*8;
        float2 v = *reinterpret_cast<const float2*>(&src[(long)(k0+kr)*N + n0 + 2*tx]);
        t[kr][2*tx]   = v.x;
        t[kr][2*tx+1] = v.y;
    }
    __syncthreads();
#pragma unroll
    for (int j = 0; j < 8; j++) {
        int n = ty + j*8;
        __half2 h = __floats2half2_rn(t[2*tx][n], t[2*tx+1][n]);
        *reinterpret_cast<__half2*>(&dst[(long)(n0+n)*K + k0 + 2*tx]) = h;
    }
}

// ---------------- rmsnorm over HID (writes fp32 + fp16) ----------------
__global__ void rmsnorm_k(const float* __restrict__ x, const float* __restrict__ w,
                          float* __restrict__ y, __half* __restrict__ yh)
{
    int row = blockIdx.x;
    const float* xr = x + (long)row*HID;
    float ss = 0.f;
    for (int i = threadIdx.x; i < HID; i += blockDim.x) { float v = xr[i]; ss += v*v; }
    __shared__ float red[32];
    for (int o = 16; o > 0; o >>= 1) ss += __shfl_xor_sync(0xffffffffu, ss, o);
    int warp = threadIdx.x >> 5, lane = threadIdx.x & 31;
    if (lane == 0) red[warp] = ss;
    __syncthreads();
    if (warp == 0) {
        ss = (lane < (blockDim.x >> 5)) ? red[lane] : 0.f;
        for (int o = 16; o > 0; o >>= 1) ss += __shfl_xor_sync(0xffffffffu, ss, o);
        if (lane == 0) red[0] = ss;
    }
    __syncthreads();
    float r = rsqrtf(red[0] / (float)HID + EPSV);
    for (int i = threadIdx.x; i < HID; i += blockDim.x) {
        float v = xr[i] * r * w[i];
        y [(long)row*HID + i] = v;
        yh[(long)row*HID + i] = __float2half(v);
    }
}

// ---------------- rope tables ----------------
__global__ void rope_tab_k(float* __restrict__ cosT, float* __restrict__ sinT)
{
    int s = blockIdx.x;
    int i = threadIdx.x;
    float inv = expf(-((float)(2*i) / (float)HDIM) * logf(1000000.0f));
    float ang = (float)s * inv;
    cosT[s*(HDIM/2)+i] = cosf(ang);
    sinT[s*(HDIM/2)+i] = sinf(ang);
}

// ---------------- per-head rmsnorm + rope, fp16 in-place; q+k heads in one grid ----------------
__global__ void qknr_k(__half* __restrict__ qkv,
                       const float* __restrict__ qnw, const float* __restrict__ knw,
                       const float* __restrict__ cosT, const float* __restrict__ sinT)
{
    long bh = blockIdx.x;
    int t = (int)(bh / (NHEAD + NKVH));
    int hh = (int)(bh % (NHEAD + NKVH));
    const float* nw = (hh < NHEAD) ? qnw : knw;
    int s = t & (SEQ-1);
    int d = threadIdx.x;
    __half* xp = qkv + (long)t*QKVN + hh*HDIM;
    float v = __half2float(xp[d]);
    float ss = v*v;
    for (int o = 16; o > 0; o >>= 1) ss += __shfl_xor_sync(0xffffffffu, ss, o);
    __shared__ float red[4];
    if ((threadIdx.x & 31) == 0) red[threadIdx.x >> 5] = ss;
    __syncthreads();
    float tot = red[0]+red[1]+red[2]+red[3];
    float r = rsqrtf(tot / (float)HDIM + EPSV);
    float xn = v * r * nw[d];
    __shared__ float xsh[HDIM];
    xsh[d] = xn;
    __syncthreads();
    float c, sn, oth;
    if (d < HDIM/2) { c = cosT[s*(HDIM/2)+d];          sn = sinT[s*(HDIM/2)+d];          oth = -xsh[d+HDIM/2]; }
    else            { c = cosT[s*(HDIM/2)+d-HDIM/2];   sn = sinT[s*(HDIM/2)+d-HDIM/2];   oth =  xsh[d-HDIM/2]; }
    xp[d] = __float2half(xn*c + oth*sn);
}

// ---------------- fp16 tensor-core flash attention (packed fp16 qkv input) ----------------
#define KPITCH 136
#define VPITCH 136
#define PPITCH 72
#define FLASHH_SMEM_BYTES ((64*KPITCH + 64*VPITCH + 64*PPITCH)*2)

__global__ void __launch_bounds__(128)
flash_h_k(const __half* __restrict__ qkv, __half* __restrict__ og)
{
    extern __shared__ __half fsh[];
    uint32_t sb = smem_u32(fsh);
    uint32_t KsU = sb;
    uint32_t VsU = sb + (uint32_t)(64*KPITCH)*2;
    uint32_t PsU = VsU + (uint32_t)(64*VPITCH)*2;
    __half* Ps = fsh + 64*KPITCH + 64*VPITCH;

    int qt = blockIdx.x, h = blockIdx.y, b = blockIdx.z;
    int kvh = h / GQA;
    int qs0 = qt*64;
    int tid = threadIdx.x, w = tid >> 5, lane = tid & 31;
    int g = lane >> 2, tg = lane & 3;
    float scale = rsqrtf((float)HDIM);

    uint32_t qa[8][4];
    {
        const __half* q0 = qkv + (long)(b*SEQ + qs0 + w*16 + g)*QKVN + h*HDIM;
        const __half* q8 = q0 + 8L*QKVN;
#pragma unroll
        for (int ks = 0; ks < 8; ks++) {
            int kb = ks*16;
            qa[ks][0] = packh2(__half2float(q0[kb+2*tg])*scale,   __half2float(q0[kb+2*tg+1])*scale);
            qa[ks][1] = packh2(__half2float(q8[kb+2*tg])*scale,   __half2float(q8[kb+2*tg+1])*scale);
            qa[ks][2] = packh2(__half2float(q0[kb+8+2*tg])*scale, __half2float(q0[kb+8+2*tg+1])*scale);
            qa[ks][3] = packh2(__half2float(q8[kb+8+2*tg])*scale, __half2float(q8[kb+8+2*tg+1])*scale);
        }
    }

    float m0 = -1e30f, m1 = -1e30f, l0 = 0.f, l1 = 0.f;
    float oac[16][4];
#pragma unroll
    for (int nt = 0; nt < 16; nt++)
#pragma unroll
        for (int r = 0; r < 4; r++) oac[nt][r] = 0.f;

    long kbase = (long)(b*SEQ)*QKVN + NHEAD*HDIM + kvh*HDIM;
    long vbase = kbase + (long)NKVH*HDIM;
    int pr0 = (w*16+g)*PPITCH, pr1 = (w*16+g+8)*PPITCH;

    uint32_t kFrag = KsU + (uint32_t)(((((lane>>4)<<3) + (lane&7))*KPITCH + ((lane>>3)&1)*8)*2);
    uint32_t pFrag = PsU + (uint32_t)(((w*16 + (lane&15))*PPITCH + ((lane>>4)&1)*8)*2);
    uint32_t vFrag = VsU + (uint32_t)(((lane&15)*VPITCH + ((lane>>4)<<3))*2);

    for (int jt = 0; jt <= qt; jt++) {
        __syncthreads();
        {
            const __half* kr = qkv + kbase + (long)(jt*64)*QKVN;
#pragma unroll
            for (int i = 0; i < 8; i++) {
                int idx = i*128 + tid;
                int r = idx >> 4, c = idx & 15;
                cp_async16(KsU + (uint32_t)(r*KPITCH + c*8)*2, kr + (long)r*QKVN + c*8, 16);
            }
            cp_commit();
            const __half* vr = qkv + vbase + (long)(jt*64)*QKVN;
#pragma unroll
            for (int i = 0; i < 8; i++) {
                int idx = i*128 + tid;
                int r = idx >> 4, c = idx & 15;
                cp_async16(VsU + (uint32_t)(r*VPITCH + c*8)*2, vr + (long)r*QKVN + c*8, 16);
            }
            cp_commit();
        }
        cp_wait<1>(); __syncthreads();

        float sacc[8][4];
#pragma unroll
        for (int nt = 0; nt < 8; nt++)
#pragma unroll
            for (int r = 0; r < 4; r++) sacc[nt][r] = 0.f;
#pragma unroll
        for (int ks = 0; ks < 8; ks++) {
#pragma unroll
            for (int ng = 0; ng < 4; ng++) {
                uint32_t r0, r1, r2, r3;
                LDSM_X4(r0, r1, r2, r3, kFrag + (uint32_t)(ng*16*KPITCH)*2 + ks*32);
                mma_f16(sacc[ng*2],   qa[ks][0], qa[ks][1], qa[ks][2], qa[ks][3], r0, r1);
                mma_f16(sacc[ng*2+1], qa[ks][0], qa[ks][1], qa[ks][2], qa[ks][3], r2, r3);
            }
        }
        int row0 = qs0 + w*16 + g, row1 = row0 + 8;
        if (jt == qt) {
            int cb = jt*64;
#pragma unroll
            for (int nt = 0; nt < 8; nt++) {
                int c0 = cb + nt*8 + 2*tg;
                if (c0   > row0) sacc[nt][0] = -1e30f;
                if (c0+1 > row0) sacc[nt][1] = -1e30f;
                if (c0   > row1) sacc[nt][2] = -1e30f;
                if (c0+1 > row1) sacc[nt][3] = -1e30f;
            }
        }
        float mx0 = m0, mx1 = m1;
#pragma unroll
        for (int nt = 0; nt < 8; nt++) {
            mx0 = fmaxf(mx0, fmaxf(sacc[nt][0], sacc[nt][1]));
            mx1 = fmaxf(mx1, fmaxf(sacc[nt][2], sacc[nt][3]));
        }
        mx0 = fmaxf(mx0, __shfl_xor_sync(0xffffffffu, mx0, 1));
        mx0 = fmaxf(mx0, __shfl_xor_sync(0xffffffffu, mx0, 2));
        mx1 = fmaxf(mx1, __shfl_xor_sync(0xffffffffu, mx1, 1));
        mx1 = fmaxf(mx1, __shfl_xor_sync(0xffffffffu, mx1, 2));
        float c0 = expf(m0 - mx0), c1 = expf(m1 - mx1);
        float s0 = 0.f, s1 = 0.f;
#pragma unroll
        for (int nt = 0; nt < 8; nt++) {
            sacc[nt][0] = expf(sacc[nt][0] - mx0);
            sacc[nt][1] = expf(sacc[nt][1] - mx0);
            sacc[nt][2] = expf(sacc[nt][2] - mx1);
            sacc[nt][3] = expf(sacc[nt][3] - mx1);
            s0 += sacc[nt][0] + sacc[nt][1];
            s1 += sacc[nt][2] + sacc[nt][3];
        }
        s0 += __shfl_xor_sync(0xffffffffu, s0, 1);
        s0 += __shfl_xor_sync(0xffffffffu, s0, 2);
        s1 += __shfl_xor_sync(0xffffffffu, s1, 1);
        s1 += __shfl_xor_sync(0xffffffffu, s1, 2);
        l0 = l0*c0 + s0;  l1 = l1*c1 + s1;  m0 = mx0;  m1 = mx1;
#pragma unroll
        for (int nt = 0; nt < 16; nt++) {
            oac[nt][0] *= c0; oac[nt][1] *= c0;
            oac[nt][2] *= c1; oac[nt][3] *= c1;
        }
#pragma unroll
        for (int nt = 0; nt < 8; nt++) {
            int pc = nt*8 + 2*tg;
            *reinterpret_cast<__half2*>(Ps + pr0 + pc) = __floats2half2_rn(sacc[nt][0], sacc[nt][1]);
            *reinterpret_cast<__half2*>(Ps + pr1 + pc) = __floats2half2_rn(sacc[nt][2], sacc[nt][3]);
        }
        cp_wait<0>(); __syncthreads();

#pragma unroll
        for (int ks = 0; ks < 4; ks++) {
            uint32_t a0, a1, a2, a3;
            LDSM_X4(a0, a1, a2, a3, pFrag + ks*32);
#pragma unroll
            for (int ng = 0; ng < 8; ng++) {
                uint32_t r0, r1, r2, r3;
                LDSM_X4_T(r0, r1, r2, r3, vFrag + (uint32_t)(ks*16*VPITCH)*2 + ng*32);
                mma_f16(oac[ng*2],   a0, a1, a2, a3, r0, r1);
                mma_f16(oac[ng*2+1], a0, a1, a2, a3, r2, r3);
            }
        }
    }

    float i0 = 1.f/l0, i1 = 1.f/l1;
    long o0 = ((long)(b*SEQ + qs0 + w*16 + g)*NHEAD + h)*HDIM;
    long o8 = o0 + 8L*NHEAD*HDIM;
#pragma unroll
    for (int nt = 0; nt < 16; nt++) {
        int c = nt*8 + 2*tg;
        *reinterpret_cast<__half2*>(&og[o0+c]) = __floats2half2_rn(oac[nt][0]*i0, oac[nt][1]*i0);
        *reinterpret_cast<__half2*>(&og[o8+c]) = __floats2half2_rn(oac[nt][2]*i1, oac[nt][3]*i1);
    }
}

// ---------------- fp16 mma GEMM: 128x128x64, 256 thr (2x4 warps, 64x32 tiles), ldmatrix, 3-stage ----------------
// C[M,N] = A[M,K] @ B^T, B stored [N][K] fp16.  K must be a multiple of 64.
// EPI: 0=store f32, 1=resid add(extra), 3=C += acc*extra[row], 4=Ch = half(acc)
#define HPITCH 72
#define TBUF_H (128*HPITCH)
#define STAGE_B (2*TBUF_H*2)
#define NSTAGE 3
#define MMH_SMEM_BYTES (NSTAGE*STAGE_B)

template<int EPI, bool AIDX, bool EXPERT>
__global__ void __launch_bounds__(256, 2)
mmh_k(int M, int N, int Kd,
      const __half* __restrict__ A, int lda,
      const __half* __restrict__ B, long strideB,
      float* __restrict__ C, __half* __restrict__ Ch, int ldc,
      const int* __restrict__ offs, const int* __restrict__ aidx,
      const float* __restrict__ extra)
{
    extern __shared__ __align__(16) char smh[];
    uint32_t sb = smem_u32(smh);

    int rbase = 0, mrows = M;
    const __half* Bp = B;
    if (EXPERT) {
        int e = blockIdx.z;
        rbase = offs[e];
        mrows = offs[e+1] - rbase;
        Bp = B + (long)e * strideB;
    }
    int bm0 = blockIdx.y * 128;
    if (bm0 >= mrows) return;
    int bn0 = blockIdx.x * 128;

    int tid = threadIdx.x, lane = tid & 31, wid = tid >> 5;
    int g = lane >> 2, tg = lane & 3;
    int warp_m = wid & 1, warp_n = wid >> 1;

    // staging: thread covers row tid>>1, 64 contiguous bytes at half-offset (tid&1)*32
    const char* aptr;
    uint32_t aok;
    {
        int lr = bm0 + (tid >> 1);
        if (lr < mrows) {
            long gr = AIDX ? (long)aidx[rbase + lr] : (long)(rbase + lr);
            aptr = (const char*)(A + gr*(long)lda + (tid & 1)*32);
            aok = 16;
        } else { aptr = (const char*)A; aok = 0; }
    }
    const char* bptr = (const char*)(Bp + (long)(bn0 + (tid >> 1))*Kd + (tid & 1)*32);
    uint32_t aoff = (uint32_t)((tid >> 1)*HPITCH + (tid & 1)*32)*2;
    uint32_t boff = (uint32_t)(TBUF_H + (tid >> 1)*HPITCH + (tid & 1)*32)*2;

    uint32_t aFragB = (uint32_t)((warp_m*64 + (lane & 15))*HPITCH + ((lane >> 4) & 1)*8)*2;
    uint32_t bFragB = (uint32_t)(TBUF_H + (warp_n*32 + ((lane >> 4) << 3) + (lane & 7))*HPITCH
                                 + ((lane >> 3) & 1)*8)*2;

    float acc[4][4][4];
#pragma unroll
    for (int mt = 0; mt < 4; mt++)
#pragma unroll
        for (int nt = 0; nt < 4; nt++)
#pragma unroll
            for (int r = 0; r < 4; r++) acc[mt][nt][r] = 0.f;

    int nc = Kd >> 6;   // 64-wide K chunks

#pragma unroll
    for (int pc = 0; pc < 2; pc++) {
        if (pc < nc) {
            uint32_t s0 = sb + pc*STAGE_B;
            long kadv = (long)pc*128;   // bytes per 64-half chunk
#pragma unroll
            for (int seg = 0; seg < 4; seg++) {
                cp_async16(s0 + aoff + seg*16, aptr + kadv + seg*16, aok);
                cp_async16(s0 + boff + seg*16, bptr + kadv + seg*16, 16);
            }
        }
        cp_commit();
    }

    for (int c = 0; c < nc; c++) {
        int p = c % NSTAGE;
        cp_wait<1>();
        __syncthreads();
        if (c + 2 < nc) {
            int q = (c + 2) % NSTAGE;
            uint32_t s0 = sb + q*STAGE_B;
            long kadv = (long)(c + 2)*128;
#pragma unroll
            for (int seg = 0; seg < 4; seg++) {
                cp_async16(s0 + aoff + seg*16, aptr + kadv + seg*16, aok);
                cp_async16(s0 + boff + seg*16, bptr + kadv + seg*16, 16);
            }
        }
        cp_commit();

        uint32_t aB = sb + p*STAGE_B + aFragB;
        uint32_t bB = sb + p*STAGE_B + bFragB;
#pragma unroll
        for (int ks = 0; ks < 4; ks++) {
            uint32_t a[4][4];
#pragma unroll
            for (int mt = 0; mt < 4; mt++)
                LDSM_X4(a[mt][0], a[mt][1], a[mt][2], a[mt][3],
                        aB + (uint32_t)(mt*16*HPITCH)*2 + ks*32);
            uint32_t bq[2][4];
#pragma unroll
            for (int ntp = 0; ntp < 2; ntp++)
                LDSM_X4(bq[ntp][0], bq[ntp][1], bq[ntp][2], bq[ntp][3],
                        bB + (uint32_t)(ntp*16*HPITCH)*2 + ks*32);
#pragma unroll
            for (int mt = 0; mt < 4; mt++)
#pragma unroll
                for (int nt = 0; nt < 4; nt++)
                    mma_f16(acc[mt][nt], a[mt][0], a[mt][1], a[mt][2], a[mt][3],
                            bq[nt >> 1][(nt & 1)*2], bq[nt >> 1][(nt & 1)*2 + 1]);
        }
    }

#pragma unroll
    for (int mt = 0; mt < 4; mt++) {
#pragma unroll
        for (int nt = 0; nt < 4; nt++) {
            int col = bn0 + warp_n*32 + nt*8 + 2*tg;
#pragma unroll
            for (int half = 0; half < 2; half++) {
                int lr = warp_m*64 + mt*16 + g + half*8;
                int grow = bm0 + lr;
                if (grow >= mrows) continue;
                long cr = rbase + grow;
                float v0 = acc[mt][nt][half*2+0];
                float v1 = acc[mt][nt][half*2+1];
                long o0 = cr*(long)ldc + col;
                if (EPI == 0) {
                    C[o0] = v0; C[o0+1] = v1;
                } else if (EPI == 1) {
                    C[o0]   = extra[o0]   + v0;
                    C[o0+1] = extra[o0+1] + v1;
                } else if (EPI == 3) {
                    float s = extra[grow];
                    C[o0]   += v0 * s;
                    C[o0+1] += v1 * s;
                } else if (EPI == 4) {
                    *reinterpret_cast<__half2*>(&Ch[o0]) = __floats2half2_rn(v0, v1);
                }
            }
        }
    }
}

// ---------------- silu-mul ----------------
__global__ void silumul_k(const __half* __restrict__ gu, __half* __restrict__ out, int W)
{
    long r = blockIdx.x;
    const __half2* gp = reinterpret_cast<const __half2*>(gu + r*(long)(2*W));
    const __half2* up = reinterpret_cast<const __half2*>(gu + r*(long)(2*W) + W);
    __half2* op = reinterpret_cast<__half2*>(out + r*(long)W);
    for (int j = threadIdx.x; j < W/2; j += blockDim.x) {
        float2 gf = __half22float2(gp[j]);
        float2 uf = __half22float2(up[j]);
        op[j] = __floats2half2_rn(gf.x / (1.f + expf(-gf.x)) * uf.x,
                                  gf.y / (1.f + expf(-gf.y)) * uf.y);
    }
}

// ---------------- router (+ fused shared-expert gate + expert counting) ----------------
__global__ void router_k(const float* __restrict__ x2, const float* __restrict__ Wr,
                         const float* __restrict__ Wshg,
                         int* __restrict__ topi, float* __restrict__ topw,
                         float* __restrict__ sig, int* __restrict__ cnt)
{
    int t = blockIdx.x;
    __shared__ float xs[HID];
    __shared__ float pr[NEXP];
    __shared__ float sred[4];
    for (int i = threadIdx.x; i < HID; i += blockDim.x) xs[i] = x2[(long)t*HID + i];
    __syncthreads();
    float sdot = 0.f;
    for (int i = threadIdx.x; i < HID; i += blockDim.x) sdot += xs[i] * Wshg[i];
    for (int o = 16; o > 0; o >>= 1) sdot += __shfl_xor_sync(0xffffffffu, sdot, o);
    if ((threadIdx.x & 31) == 0) sred[threadIdx.x >> 5] = sdot;
    if (threadIdx.x < NEXP) {
        int e = threadIdx.x;
        float d = 0.f;
        for (int i = 0; i < HID; i++) d += xs[i] * Wr[i*NEXP + e];
        pr[e] = d;
    }
    __syncthreads();
    if (threadIdx.x == 0) {
        sig[t] = 1.f / (1.f + expf(-(sred[0]+sred[1]+sred[2]+sred[3])));
        float mx = -1e30f;
        for (int e = 0; e < NEXP; e++) mx = fmaxf(mx, pr[e]);
        float p[NEXP]; float sm2 = 0.f;
        for (int e = 0; e < NEXP; e++) { p[e] = expf(pr[e]-mx); sm2 += p[e]; }
        for (int e = 0; e < NEXP; e++) p[e] /= sm2;
        float tw = 0.f;
        int   idx[TOPK]; float val[TOPK];
        for (int kk = 0; kk < TOPK; kk++) {
            int bi = 0; float bv = -1.f;
            for (int e = 0; e < NEXP; e++) if (p[e] > bv) { bv = p[e]; bi = e; }
            idx[kk] = bi; val[kk] = bv; p[bi] = -2.f; tw += bv;
        }
        for (int kk = 0; kk < TOPK; kk++) {
            topi[t*TOPK+kk] = idx[kk];
            topw[t*TOPK+kk] = val[kk] / tw;
            atomicAdd(&cnt[idx[kk]], 1);
        }
    }
}

// ---------------- routing build ----------------
__global__ void zero32_k(int* cnt) { if (threadIdx.x < NEXP) cnt[threadIdx.x] = 0; }
__global__ void scan_k(const int* __restrict__ cnt, int* __restrict__ off, int* __restrict__ cur)
{
    if (threadIdx.x == 0) {
        int a = 0;
        for (int e = 0; e < NEXP; e++) { off[e] = a; cur[e] = a; a += cnt[e]; }
        off[NEXP] = a;
    }
}
__global__ void fill_k(const int* __restrict__ topi, int* __restrict__ cur,
                       int* __restrict__ ptok, int* __restrict__ ppos)
{
    int i = blockIdx.x*256 + threadIdx.x;
    if (i < NPAIR) {
        int e = topi[i];
        int p = atomicAdd(&cur[e], 1);
        ptok[p] = i / TOPK;
        ppos[i] = p;
    }
}

// ---------------- MoE reduction (fp16 down, half2 vectorized) ----------------
__global__ void moe_reduce_k(const __half* __restrict__ down, const int* __restrict__ ppos,
                             const float* __restrict__ topw, const float* __restrict__ h,
                             float* __restrict__ out)
{
    int t = blockIdx.x;
    long pos[TOPK]; float w[TOPK];
#pragma unroll
    for (int kk = 0; kk < TOPK; kk++) { pos[kk] = ppos[t*TOPK+kk]; w[kk] = topw[t*TOPK+kk]; }
    const float2* hp = reinterpret_cast<const float2*>(h + (long)t*HID);
    float2* op = reinterpret_cast<float2*>(out + (long)t*HID);
    for (int c = threadIdx.x; c < HID/2; c += blockDim.x) {
        float2 s = hp[c];
#pragma unroll
        for (int kk = 0; kk < TOPK; kk++) {
            float2 d = __half22float2(*reinterpret_cast<const __half2*>(&down[pos[kk]*HID + 2*c]));
            s.x += d.x * w[kk];
            s.y += d.y * w[kk];
        }
        op[c] = s;
    }
}

// ---------------- host launch ----------------
extern "C" void kernel_launch(void* const* d_in, const int* in_sizes, int n_in,
                              void* d_out, int out_size)
{
    (void)in_sizes; (void)out_size;
    if (n_in < 17) return;
    const float* hidden = (const float*)d_in[0];
    const float* ln1    = (const float*)d_in[1];
    const float* ln2    = (const float*)d_in[2];
    const float* qnw    = (const float*)d_in[3];
    const float* knw    = (const float*)d_in[4];
    const float* Wq     = (const float*)d_in[5];
    const float* Wk     = (const float*)d_in[6];
    const float* Wv     = (const float*)d_in[7];
    const float* Wo     = (const float*)d_in[8];
    const float* Wr     = (const float*)d_in[9];
    const float* Weg    = (const float*)d_in[10];
    const float* Weu    = (const float*)d_in[11];
    const float* Wed    = (const float*)d_in[12];
    const float* Wsg    = (const float*)d_in[13];
    const float* Wsu    = (const float*)d_in[14];
    const float* Wsd    = (const float*)d_in[15];
    const float* Wshg   = (const float*)d_in[16];
    float* out = (float*)d_out;

    float *xn, *hb, *cosT, *sinT, *topw, *sig;
    int *topi, *cnt, *off, *cur, *ptok, *ppos;
    __half *qkvh, *xh, *atth, *guh, *acth, *downh, *gsh, *shh;
    __half *WqkvT, *WoT, *WguT, *WedT, *WsguT, *WsdT;
    cudaGetSymbolAddress((void**)&xn,    g_xn);
    cudaGetSymbolAddress((void**)&hb,    g_h);
    cudaGetSymbolAddress((void**)&cosT,  g_cos);
    cudaGetSymbolAddress((void**)&sinT,  g_sin);
    cudaGetSymbolAddress((void**)&topi,  g_topi);
    cudaGetSymbolAddress((void**)&topw,  g_topw);
    cudaGetSymbolAddress((void**)&cnt,   g_cnt);
    cudaGetSymbolAddress((void**)&off,   g_off);
    cudaGetSymbolAddress((void**)&cur,   g_cur);
    cudaGetSymbolAddress((void**)&ptok,  g_ptok);
    cudaGetSymbolAddress((void**)&ppos,  g_ppos);
    cudaGetSymbolAddress((void**)&sig,   g_sig);
    cudaGetSymbolAddress((void**)&qkvh,  g_qkvh);
    cudaGetSymbolAddress((void**)&xh,    g_xh);
    cudaGetSymbolAddress((void**)&atth,  g_atth);
    cudaGetSymbolAddress((void**)&guh,   g_guh);
    cudaGetSymbolAddress((void**)&acth,  g_acth);
    cudaGetSymbolAddress((void**)&downh, g_downh);
    cudaGetSymbolAddress((void**)&gsh,   g_gsh);
    cudaGetSymbolAddress((void**)&shh,   g_shh);
    cudaGetSymbolAddress((void**)&WqkvT, g_Wqkv);
    cudaGetSymbolAddress((void**)&WoT,   g_WoT);
    cudaGetSymbolAddress((void**)&WguT,  g_WguT);
    cudaGetSymbolAddress((void**)&WedT,  g_WedT);
    cudaGetSymbolAddress((void**)&WsguT, g_WsguT);
    cudaGetSymbolAddress((void**)&WsdT,  g_WsdT);

    cudaFuncSetAttribute(flash_h_k, cudaFuncAttributeMaxDynamicSharedMemorySize, FLASHH_SMEM_BYTES);
    cudaFuncSetAttribute(mmh_k<1,false,false>, cudaFuncAttributeMaxDynamicSharedMemorySize, MMH_SMEM_BYTES);
    cudaFuncSetAttribute(mmh_k<3,false,false>, cudaFuncAttributeMaxDynamicSharedMemorySize, MMH_SMEM_BYTES);
    cudaFuncSetAttribute(mmh_k<4,false,false>, cudaFuncAttributeMaxDynamicSharedMemorySize, MMH_SMEM_BYTES);
    cudaFuncSetAttribute(mmh_k<4,true,true>,   cudaFuncAttributeMaxDynamicSharedMemorySize, MMH_SMEM_BYTES);
    cudaFuncSetAttribute(mmh_k<4,false,true>,  cudaFuncAttributeMaxDynamicSharedMemorySize, MMH_SMEM_BYTES);

    dim3 tb(32, 8);
    // --- weight transpose+fp16 conversion (once per launch), 64x64 tiles ---
    tcvt_k<<<dim3(4096/64, 2048/64), tb>>>(Wq, WqkvT, HID, 4096, 0, 0);
    tcvt_k<<<dim3( 512/64, 2048/64), tb>>>(Wk, WqkvT + (long)4096*HID, HID, 512, 0, 0);
    tcvt_k<<<dim3( 512/64, 2048/64), tb>>>(Wv, WqkvT + (long)4608*HID, HID, 512, 0, 0);
    tcvt_k<<<dim3(2048/64, 4096/64), tb>>>(Wo, WoT, 4096, 2048, 0, 0);
    tcvt_k<<<dim3(EI/64, HID/64, NEXP), tb>>>(Weg, WguT,                HID, EI, (long)HID*EI, (long)2*EI*HID);
    tcvt_k<<<dim3(EI/64, HID/64, NEXP), tb>>>(Weu, WguT + (long)EI*HID, HID, EI, (long)HID*EI, (long)2*EI*HID);
    tcvt_k<<<dim3(HID/64, EI/64, NEXP), tb>>>(Wed, WedT, EI, HID, (long)EI*HID, (long)EI*HID);
    tcvt_k<<<dim3(SI/64, HID/64), tb>>>(Wsg, WsguT,                HID, SI, 0, 0);
    tcvt_k<<<dim3(SI/64, HID/64), tb>>>(Wsu, WsguT + (long)SI*HID, HID, SI, 0, 0);
    tcvt_k<<<dim3(HID/64, SI/64), tb>>>(Wsd, WsdT, SI, HID, 0, 0);

    // --- attention block ---
    rmsnorm_k<<<T_TOK, 256>>>(hidden, ln1, xn, xh);

    mmh_k<4,false,false><<<dim3(QKVN/128, 32), 256, MMH_SMEM_BYTES>>>(
        T_TOK, QKVN, HID, xh, HID, WqkvT, 0, nullptr, qkvh, QKVN, nullptr, nullptr, nullptr);

    rope_tab_k<<<SEQ, HDIM/2>>>(cosT, sinT);
    qknr_k<<<T_TOK*(NHEAD+NKVH), HDIM>>>(qkvh, qnw, knw, cosT, sinT);

    flash_h_k<<<dim3(SEQ/64, NHEAD, BATCH), 128, FLASHH_SMEM_BYTES>>>(qkvh, atth);

    // h = hidden + att @ Wo
    mmh_k<1,false,false><<<dim3(16, 32), 256, MMH_SMEM_BYTES>>>(
        T_TOK, HID, NHEAD*HDIM, atth, NHEAD*HDIM, WoT, 0, hb, nullptr, HID, nullptr, nullptr, hidden);

    // --- MoE block ---
    rmsnorm_k<<<T_TOK, 256>>>(hb, ln2, xn, xh);

    zero32_k<<<1, 32>>>(cnt);
    router_k<<<T_TOK, 128>>>(xn, Wr, Wshg, topi, topw, sig, cnt);
    scan_k<<<1, 32>>>(cnt, off, cur);
    fill_k<<<(NPAIR+255)/256, 256>>>(topi, cur, ptok, ppos);

    // experts: merged gate|up -> guh; silu-mul -> acth; down -> downh
    mmh_k<4,true,true><<<dim3(2*EI/128, 32, NEXP), 256, MMH_SMEM_BYTES>>>(
        0, 2*EI, HID, xh, HID, WguT, (long)2*EI*HID, nullptr, guh, 2*EI, off, ptok, nullptr);
    silumul_k<<<NPAIR, 256>>>(guh, acth, EI);
    mmh_k<4,false,true><<<dim3(HID/128, 32, NEXP), 256, MMH_SMEM_BYTES>>>(
        0, HID, EI, acth, EI, WedT, (long)HID*EI, nullptr, downh, HID, off, nullptr, nullptr);

    moe_reduce_k<<<T_TOK, 256>>>(downh, ppos, topw, hb, out);

    // --- shared expert: merged gate|up -> gsh; silu-mul -> shh; down (rowscale-add) ---
    mmh_k<4,false,false><<<dim3(2*SI/128, 32), 256, MMH_SMEM_BYTES>>>(
        T_TOK, 2*SI, HID, xh, HID, WsguT, 0, nullptr, gsh, 2*SI, nullptr, nullptr, nullptr);
    silumul_k<<<T_TOK, 256>>>(gsh, shh, SI);
    mmh_k<3,false,false><<<dim3(HID/128, 32), 256, MMH_SMEM_BYTES>>>(
        T_TOK, HID, SI, shh, SI, WsdT, 0, out, nullptr, HID, nullptr, nullptr, sig);
}

// round 16
// speedup vs baseline: 1.1579x; 1.1579x over previous
#include <cuda_runtime.h>
#include <cuda_fp16.h>
#include <math.h>
#include <stdint.h>

// ---------------- problem constants ----------------
#define T_TOK 4096
#define HID   2048
#define SEQ   1024
#define BATCH 4
#define NHEAD 32
#define NKVH  4
#define HDIM  128
#define NEXP  32
#define TOPK  8
#define EI    768
#define SI    4096
#define GQA   8
#define EPSV  1e-6f
#define QKVN  (NHEAD*HDIM + 2*NKVH*HDIM)   // 5120
#define NPAIR (T_TOK*TOPK)

// ---------------- scratch (fp32) ----------------
__device__ float g_xn  [T_TOK*HID];
__device__ float g_h   [T_TOK*HID];
__device__ float g_cos[SEQ*(HDIM/2)];
__device__ float g_sin[SEQ*(HDIM/2)];
__device__ int   g_topi[NPAIR];
__device__ float g_topw[NPAIR];
__device__ int   g_cnt[NEXP];
__device__ int   g_off[NEXP+1];
__device__ int   g_cur[NEXP];
__device__ int   g_ptok[NPAIR];
__device__ int   g_ppos[NPAIR];
__device__ float g_sig[T_TOK];
// ---------------- scratch (fp16) ----------------
__device__ __half g_qkvh [(long)T_TOK*QKVN];
__device__ __half g_xh   [T_TOK*HID];
__device__ __half g_atth [T_TOK*NHEAD*HDIM];
__device__ __half g_guh  [(long)NPAIR*2*EI];
__device__ __half g_acth [(long)NPAIR*EI];
__device__ __half g_downh[(long)NPAIR*HID];
__device__ __half g_gsh  [(long)T_TOK*2*SI];
__device__ __half g_shh  [T_TOK*SI];
// fp16 transposed weights [N][K]
__device__ __half g_Wqkv[QKVN*HID];
__device__ __half g_WoT [HID*NHEAD*HDIM];
__device__ __half g_WguT[(long)NEXP*2*EI*HID];
__device__ __half g_WedT[(long)NEXP*HID*EI];
__device__ __half g_WsguT[(long)2*SI*HID];
__device__ __half g_WsdT[HID*SI];

// ---------------- helpers ----------------
__device__ __forceinline__ uint32_t smem_u32(const void* p){
    uint32_t a;
    asm("{ .reg .u64 t; cvta.to.shared.u64 t, %1; cvt.u32.u64 %0, t; }" : "=r"(a) : "l"(p));
    return a;
}
__device__ __forceinline__ void cp_async16(uint32_t saddr, const void* gaddr, uint32_t sz){
    asm volatile("cp.async.cg.shared.global [%0], [%1], 16, %2;"
        :: "r"(saddr), "l"(gaddr), "r"(sz) : "memory");
}
__device__ __forceinline__ void cp_commit(){
    asm volatile("cp.async.commit_group;" ::: "memory");
}
template<int N>
__device__ __forceinline__ void cp_wait(){
    asm volatile("cp.async.wait_group %0;" :: "n"(N) : "memory");
}
__device__ __forceinline__ void mma_f16(float* c, uint32_t a0, uint32_t a1, uint32_t a2, uint32_t a3,
                                        uint32_t b0, uint32_t b1)
{
    asm volatile("mma.sync.aligned.m16n8k16.row.col.f32.f16.f16.f32 "
        "{%0,%1,%2,%3}, {%4,%5,%6,%7}, {%8,%9}, {%0,%1,%2,%3};"
        : "+f"(c[0]), "+f"(c[1]), "+f"(c[2]), "+f"(c[3])
        : "r"(a0), "r"(a1), "r"(a2), "r"(a3), "r"(b0), "r"(b1));
}
#define LDSM_X4(r0, r1, r2, r3, addr) \
    asm volatile("ldmatrix.sync.aligned.m8n8.x4.shared.b16 {%0,%1,%2,%3}, [%4];" \
        : "=r"(r0), "=r"(r1), "=r"(r2), "=r"(r3) : "r"(addr))
#define LDSM_X4_T(r0, r1, r2, r3, addr) \
    asm volatile("ldmatrix.sync.aligned.m8n8.x4.trans.shared.b16 {%0,%1,%2,%3}, [%4];" \
        : "=r"(r0), "=r"(r1), "=r"(r2), "=r"(r3) : "r"(addr))
__device__ __forceinline__ uint32_t packh2(float a, float b){
    __half2 h = __floats2half2_rn(a, b);
    return *reinterpret_cast<uint32_t*>(&h);
}

// ---------------- weight transpose + fp16 convert: src[K][N] -> dst[N][K], 32(n)x64(k) tiles ----------------
__global__ void tcvt_k(const float* __restrict__ src, __half* __restrict__ dst, int K, int N,
                       long srcZ, long dstZ)
{
    __shared__ float t[64][33];
    long z = blockIdx.z;
    src += z * srcZ;
    dst += z * dstZ;
    int n0 = blockIdx.x*32, k0 = blockIdx.y*64;
    int tx = threadIdx.x, ty = threadIdx.y;
#pragma unroll
    for (int i = 0; i < 8; i++)
        t[ty + i*8][tx] = src[(long)(k0 + ty + i*8)*N + n0 + tx];
    __syncthreads();
#pragma unroll
    for (int i = 0; i < 4; i++) {
        int n = ty + i*8;
        __half2 h = __floats2half2_rn(t[2*tx][n], t[2*tx+1][n]);
        *reinterpret_cast<__half2*>(&dst[(long)(n0+n)*K + k0 + 2*tx]) = h;
    }
}

// ---------------- rmsnorm over HID (writes fp32 + fp16) ----------------
__global__ void rmsnorm_k(const float* __restrict__ x, const float* __restrict__ w,
                          float* __restrict__ y, __half* __restrict__ yh)
{
    int row = blockIdx.x;
    const float* xr = x + (long)row*HID;
    float ss = 0.f;
    for (int i = threadIdx.x; i < HID; i += blockDim.x) { float v = xr[i]; ss += v*v; }
    __shared__ float red[32];
    for (int o = 16; o > 0; o >>= 1) ss += __shfl_xor_sync(0xffffffffu, ss, o);
    int warp = threadIdx.x >> 5, lane = threadIdx.x & 31;
    if (lane == 0) red[warp] = ss;
    __syncthreads();
    if (warp == 0) {
        ss = (lane < (blockDim.x >> 5)) ? red[lane] : 0.f;
        for (int o = 16; o > 0; o >>= 1) ss += __shfl_xor_sync(0xffffffffu, ss, o);
        if (lane == 0) red[0] = ss;
    }
    __syncthreads();
    float r = rsqrtf(red[0] / (float)HID + EPSV);
    for (int i = threadIdx.x; i < HID; i += blockDim.x) {
        float v = xr[i] * r * w[i];
        y [(long)row*HID + i] = v;
        yh[(long)row*HID + i] = __float2half(v);
    }
}

// ---------------- rope tables ----------------
__global__ void rope_tab_k(float* __restrict__ cosT, float* __restrict__ sinT)
{
    int s = blockIdx.x;
    int i = threadIdx.x;
    float inv = expf(-((float)(2*i) / (float)HDIM) * logf(1000000.0f));
    float ang = (float)s * inv;
    cosT[s*(HDIM/2)+i] = cosf(ang);
    sinT[s*(HDIM/2)+i] = sinf(ang);
}

// ---------------- per-head rmsnorm + rope, fp16 in-place; q+k heads in one grid ----------------
__global__ void qknr_k(__half* __restrict__ qkv,
                       const float* __restrict__ qnw, const float* __restrict__ knw,
                       const float* __restrict__ cosT, const float* __restrict__ sinT)
{
    long bh = blockIdx.x;
    int t = (int)(bh / (NHEAD + NKVH));
    int hh = (int)(bh % (NHEAD + NKVH));
    const float* nw = (hh < NHEAD) ? qnw : knw;
    int s = t & (SEQ-1);
    int d = threadIdx.x;
    __half* xp = qkv + (long)t*QKVN + hh*HDIM;
    float v = __half2float(xp[d]);
    float ss = v*v;
    for (int o = 16; o > 0; o >>= 1) ss += __shfl_xor_sync(0xffffffffu, ss, o);
    __shared__ float red[4];
    if ((threadIdx.x & 31) == 0) red[threadIdx.x >> 5] = ss;
    __syncthreads();
    float tot = red[0]+red[1]+red[2]+red[3];
    float r = rsqrtf(tot / (float)HDIM + EPSV);
    float xn = v * r * nw[d];
    __shared__ float xsh[HDIM];
    xsh[d] = xn;
    __syncthreads();
    float c, sn, oth;
    if (d < HDIM/2) { c = cosT[s*(HDIM/2)+d];          sn = sinT[s*(HDIM/2)+d];          oth = -xsh[d+HDIM/2]; }
    else            { c = cosT[s*(HDIM/2)+d-HDIM/2];   sn = sinT[s*(HDIM/2)+d-HDIM/2];   oth =  xsh[d-HDIM/2]; }
    xp[d] = __float2half(xn*c + oth*sn);
}

// ---------------- fp16 tensor-core flash attention (packed fp16 qkv input) ----------------
#define KPITCH 136
#define VPITCH 136
#define PPITCH 72
#define FLASHH_SMEM_BYTES ((64*KPITCH + 64*VPITCH + 64*PPITCH)*2)

__global__ void __launch_bounds__(128)
flash_h_k(const __half* __restrict__ qkv, __half* __restrict__ og)
{
    extern __shared__ __half fsh[];
    uint32_t sb = smem_u32(fsh);
    uint32_t KsU = sb;
    uint32_t VsU = sb + (uint32_t)(64*KPITCH)*2;
    uint32_t PsU = VsU + (uint32_t)(64*VPITCH)*2;
    __half* Ps = fsh + 64*KPITCH + 64*VPITCH;

    int qt = blockIdx.x, h = blockIdx.y, b = blockIdx.z;
    int kvh = h / GQA;
    int qs0 = qt*64;
    int tid = threadIdx.x, w = tid >> 5, lane = tid & 31;
    int g = lane >> 2, tg = lane & 3;
    float scale = rsqrtf((float)HDIM);

    uint32_t qa[8][4];
    {
        const __half* q0 = qkv + (long)(b*SEQ + qs0 + w*16 + g)*QKVN + h*HDIM;
        const __half* q8 = q0 + 8L*QKVN;
#pragma unroll
        for (int ks = 0; ks < 8; ks++) {
            int kb = ks*16;
            qa[ks][0] = packh2(__half2float(q0[kb+2*tg])*scale,   __half2float(q0[kb+2*tg+1])*scale);
            qa[ks][1] = packh2(__half2float(q8[kb+2*tg])*scale,   __half2float(q8[kb+2*tg+1])*scale);
            qa[ks][2] = packh2(__half2float(q0[kb+8+2*tg])*scale, __half2float(q0[kb+8+2*tg+1])*scale);
            qa[ks][3] = packh2(__half2float(q8[kb+8+2*tg])*scale, __half2float(q8[kb+8+2*tg+1])*scale);
        }
    }

    float m0 = -1e30f, m1 = -1e30f, l0 = 0.f, l1 = 0.f;
    float oac[16][4];
#pragma unroll
    for (int nt = 0; nt < 16; nt++)
#pragma unroll
        for (int r = 0; r < 4; r++) oac[nt][r] = 0.f;

    long kbase = (long)(b*SEQ)*QKVN + NHEAD*HDIM + kvh*HDIM;
    long vbase = kbase + (long)NKVH*HDIM;
    int pr0 = (w*16+g)*PPITCH, pr1 = (w*16+g+8)*PPITCH;

    uint32_t kFrag = KsU + (uint32_t)(((((lane>>4)<<3) + (lane&7))*KPITCH + ((lane>>3)&1)*8)*2);
    uint32_t pFrag = PsU + (uint32_t)(((w*16 + (lane&15))*PPITCH + ((lane>>4)&1)*8)*2);
    uint32_t vFrag = VsU + (uint32_t)(((lane&15)*VPITCH + ((lane>>4)<<3))*2);

    for (int jt = 0; jt <= qt; jt++) {
        __syncthreads();
        {
            const __half* kr = qkv + kbase + (long)(jt*64)*QKVN;
#pragma unroll
            for (int i = 0; i < 8; i++) {
                int idx = i*128 + tid;
                int r = idx >> 4, c = idx & 15;
                cp_async16(KsU + (uint32_t)(r*KPITCH + c*8)*2, kr + (long)r*QKVN + c*8, 16);
            }
            cp_commit();
            const __half* vr = qkv + vbase + (long)(jt*64)*QKVN;
#pragma unroll
            for (int i = 0; i < 8; i++) {
                int idx = i*128 + tid;
                int r = idx >> 4, c = idx & 15;
                cp_async16(VsU + (uint32_t)(r*VPITCH + c*8)*2, vr + (long)r*QKVN + c*8, 16);
            }
            cp_commit();
        }
        cp_wait<1>(); __syncthreads();

        float sacc[8][4];
#pragma unroll
        for (int nt = 0; nt < 8; nt++)
#pragma unroll
            for (int r = 0; r < 4; r++) sacc[nt][r] = 0.f;
#pragma unroll
        for (int ks = 0; ks < 8; ks++) {
#pragma unroll
            for (int ng = 0; ng < 4; ng++) {
                uint32_t r0, r1, r2, r3;
                LDSM_X4(r0, r1, r2, r3, kFrag + (uint32_t)(ng*16*KPITCH)*2 + ks*32);
                mma_f16(sacc[ng*2],   qa[ks][0], qa[ks][1], qa[ks][2], qa[ks][3], r0, r1);
                mma_f16(sacc[ng*2+1], qa[ks][0], qa[ks][1], qa[ks][2], qa[ks][3], r2, r3);
            }
        }
        int row0 = qs0 + w*16 + g, row1 = row0 + 8;
        if (jt == qt) {
            int cb = jt*64;
#pragma unroll
            for (int nt = 0; nt < 8; nt++) {
                int c0 = cb + nt*8 + 2*tg;
                if (c0   > row0) sacc[nt][0] = -1e30f;
                if (c0+1 > row0) sacc[nt][1] = -1e30f;
                if (c0   > row1) sacc[nt][2] = -1e30f;
                if (c0+1 > row1) sacc[nt][3] = -1e30f;
            }
        }
        float mx0 = m0, mx1 = m1;
#pragma unroll
        for (int nt = 0; nt < 8; nt++) {
            mx0 = fmaxf(mx0, fmaxf(sacc[nt][0], sacc[nt][1]));
            mx1 = fmaxf(mx1, fmaxf(sacc[nt][2], sacc[nt][3]));
        }
        mx0 = fmaxf(mx0, __shfl_xor_sync(0xffffffffu, mx0, 1));
        mx0 = fmaxf(mx0, __shfl_xor_sync(0xffffffffu, mx0, 2));
        mx1 = fmaxf(mx1, __shfl_xor_sync(0xffffffffu, mx1, 1));
        mx1 = fmaxf(mx1, __shfl_xor_sync(0xffffffffu, mx1, 2));
        float c0 = expf(m0 - mx0), c1 = expf(m1 - mx1);
        float s0 = 0.f, s1 = 0.f;
#pragma unroll
        for (int nt = 0; nt < 8; nt++) {
            sacc[nt][0] = expf(sacc[nt][0] - mx0);
            sacc[nt][1] = expf(sacc[nt][1] - mx0);
            sacc[nt][2] = expf(sacc[nt][2] - mx1);
            sacc[nt][3] = expf(sacc[nt][3] - mx1);
            s0 += sacc[nt][0] + sacc[nt][1];
            s1 += sacc[nt][2] + sacc[nt][3];
        }
        s0 += __shfl_xor_sync(0xffffffffu, s0, 1);
        s0 += __shfl_xor_sync(0xffffffffu, s0, 2);
        s1 += __shfl_xor_sync(0xffffffffu, s1, 1);
        s1 += __shfl_xor_sync(0xffffffffu, s1, 2);
        l0 = l0*c0 + s0;  l1 = l1*c1 + s1;  m0 = mx0;  m1 = mx1;
#pragma unroll
        for (int nt = 0; nt < 16; nt++) {
            oac[nt][0] *= c0; oac[nt][1] *= c0;
            oac[nt][2] *= c1; oac[nt][3] *= c1;
        }
#pragma unroll
        for (int nt = 0; nt < 8; nt++) {
            int pc = nt*8 + 2*tg;
            *reinterpret_cast<__half2*>(Ps + pr0 + pc) = __floats2half2_rn(sacc[nt][0], sacc[nt][1]);
            *reinterpret_cast<__half2*>(Ps + pr1 + pc) = __floats2half2_rn(sacc[nt][2], sacc[nt][3]);
        }
        cp_wait<0>(); __syncthreads();

#pragma unroll
        for (int ks = 0; ks < 4; ks++) {
            uint32_t a0, a1, a2, a3;
            LDSM_X4(a0, a1, a2, a3, pFrag + ks*32);
#pragma unroll
            for (int ng = 0; ng < 8; ng++) {
                uint32_t r0, r1, r2, r3;
                LDSM_X4_T(r0, r1, r2, r3, vFrag + (uint32_t)(ks*16*VPITCH)*2 + ng*32);
                mma_f16(oac[ng*2],   a0, a1, a2, a3, r0, r1);
                mma_f16(oac[ng*2+1], a0, a1, a2, a3, r2, r3);
            }
        }
    }

    float i0 = 1.f/l0, i1 = 1.f/l1;
    long o0 = ((long)(b*SEQ + qs0 + w*16 + g)*NHEAD + h)*HDIM;
    long o8 = o0 + 8L*NHEAD*HDIM;
#pragma unroll
    for (int nt = 0; nt < 16; nt++) {
        int c = nt*8 + 2*tg;
        *reinterpret_cast<__half2*>(&og[o0+c]) = __floats2half2_rn(oac[nt][0]*i0, oac[nt][1]*i0);
        *reinterpret_cast<__half2*>(&og[o8+c]) = __floats2half2_rn(oac[nt][2]*i1, oac[nt][3]*i1);
    }
}

// ---------------- fp16 mma GEMM: 128x128x32, 256 thr (2x4 warps, 64x32 tiles), ldmatrix, 4-stage ----------------
// C[M,N] = A[M,K] @ B^T, B stored [N][K] fp16.
// EPI: 0=store f32, 1=resid add(extra), 3=C += acc*extra[row], 4=Ch = half(acc)
#define HPITCH 40
#define TBUF_H (128*HPITCH)
#define STAGE_B (2*TBUF_H*2)
#define NSTAGE 4
#define MMH_SMEM_BYTES (NSTAGE*STAGE_B)

template<int EPI, bool AIDX, bool EXPERT>
__global__ void __launch_bounds__(256, 2)
mmh_k(int M, int N, int Kd,
      const __half* __restrict__ A, int lda,
      const __half* __restrict__ B, long strideB,
      float* __restrict__ C, __half* __restrict__ Ch, int ldc,
      const int* __restrict__ offs, const int* __restrict__ aidx,
      const float* __restrict__ extra)
{
    extern __shared__ __align__(16) char smh[];
    uint32_t sb = smem_u32(smh);

    int rbase = 0, mrows = M;
    const __half* Bp = B;
    if (EXPERT) {
        int e = blockIdx.z;
        rbase = offs[e];
        mrows = offs[e+1] - rbase;
        Bp = B + (long)e * strideB;
    }
    int bm0 = blockIdx.y * 128;
    if (bm0 >= mrows) return;
    int bn0 = blockIdx.x * 128;

    int tid = threadIdx.x, lane = tid & 31, wid = tid >> 5;
    int g = lane >> 2, tg = lane & 3;
    int warp_m = wid & 1, warp_n = wid >> 1;

    const char* aptr;
    uint32_t aok;
    {
        int lr = bm0 + (tid >> 1);
        if (lr < mrows) {
            long gr = AIDX ? (long)aidx[rbase + lr] : (long)(rbase + lr);
            aptr = (const char*)(A + gr*(long)lda + (tid & 1)*16);
            aok = 16;
        } else { aptr = (const char*)A; aok = 0; }
    }
    const char* bptr = (const char*)(Bp + (long)(bn0 + (tid >> 1))*Kd + (tid & 1)*16);
    uint32_t aoff = (uint32_t)((tid >> 1)*HPITCH + (tid & 1)*16)*2;
    uint32_t boff = (uint32_t)(TBUF_H + (tid >> 1)*HPITCH + (tid & 1)*16)*2;

    uint32_t aFragB = (uint32_t)((warp_m*64 + (lane & 15))*HPITCH + ((lane >> 4) & 1)*8)*2;
    uint32_t bFragB = (uint32_t)(TBUF_H + (warp_n*32 + ((lane >> 4) << 3) + (lane & 7))*HPITCH
                                 + ((lane >> 3) & 1)*8)*2;

    float acc[4][4][4];
#pragma unroll
    for (int mt = 0; mt < 4; mt++)
#pragma unroll
        for (int nt = 0; nt < 4; nt++)
#pragma unroll
            for (int r = 0; r < 4; r++) acc[mt][nt][r] = 0.f;

    int nc = Kd >> 5;

    // prologue: stage chunks 0,1,2
#pragma unroll
    for (int pc = 0; pc < 3; pc++) {
        if (pc < nc) {
            uint32_t s0 = sb + pc*STAGE_B;
            long kadv = (long)pc*64;
            cp_async16(s0 + aoff,      aptr + kadv,      aok);
            cp_async16(s0 + aoff + 16, aptr + kadv + 16, aok);
            cp_async16(s0 + boff,      bptr + kadv,      16);
            cp_async16(s0 + boff + 16, bptr + kadv + 16, 16);
        }
        cp_commit();
    }

    for (int c = 0; c < nc; c++) {
        int p = c % NSTAGE;
        cp_wait<2>();          // pending = {c, c+1, c+2} -> group c complete
        __syncthreads();       // buffer (c+3)%4 consumed at iter c-1 -> free
        if (c + 3 < nc) {
            int q = (c + 3) % NSTAGE;
            uint32_t s0 = sb + q*STAGE_B;
            long kadv = (long)(c + 3)*64;
            cp_async16(s0 + aoff,      aptr + kadv,      aok);
            cp_async16(s0 + aoff + 16, aptr + kadv + 16, aok);
            cp_async16(s0 + boff,      bptr + kadv,      16);
            cp_async16(s0 + boff + 16, bptr + kadv + 16, 16);
        }
        cp_commit();           // always commit to keep group count regular

        uint32_t aB = sb + p*STAGE_B + aFragB;
        uint32_t bB = sb + p*STAGE_B + bFragB;
#pragma unroll
        for (int ks = 0; ks < 2; ks++) {
            uint32_t a[4][4];
#pragma unroll
            for (int mt = 0; mt < 4; mt++)
                LDSM_X4(a[mt][0], a[mt][1], a[mt][2], a[mt][3],
                        aB + (uint32_t)(mt*16*HPITCH)*2 + ks*32);
            uint32_t bq[2][4];
#pragma unroll
            for (int ntp = 0; ntp < 2; ntp++)
                LDSM_X4(bq[ntp][0], bq[ntp][1], bq[ntp][2], bq[ntp][3],
                        bB + (uint32_t)(ntp*16*HPITCH)*2 + ks*32);
#pragma unroll
            for (int mt = 0; mt < 4; mt++)
#pragma unroll
                for (int nt = 0; nt < 4; nt++)
                    mma_f16(acc[mt][nt], a[mt][0], a[mt][1], a[mt][2], a[mt][3],
                            bq[nt >> 1][(nt & 1)*2], bq[nt >> 1][(nt & 1)*2 + 1]);
        }
    }

#pragma unroll
    for (int mt = 0; mt < 4; mt++) {
#pragma unroll
        for (int nt = 0; nt < 4; nt++) {
            int col = bn0 + warp_n*32 + nt*8 + 2*tg;
#pragma unroll
            for (int half = 0; half < 2; half++) {
                int lr = warp_m*64 + mt*16 + g + half*8;
                int grow = bm0 + lr;
                if (grow >= mrows) continue;
                long cr = rbase + grow;
                float v0 = acc[mt][nt][half*2+0];
                float v1 = acc[mt][nt][half*2+1];
                long o0 = cr*(long)ldc + col;
                if (EPI == 0) {
                    C[o0] = v0; C[o0+1] = v1;
                } else if (EPI == 1) {
                    C[o0]   = extra[o0]   + v0;
                    C[o0+1] = extra[o0+1] + v1;
                } else if (EPI == 3) {
                    float s = extra[grow];
                    C[o0]   += v0 * s;
                    C[o0+1] += v1 * s;
                } else if (EPI == 4) {
                    *reinterpret_cast<__half2*>(&Ch[o0]) = __floats2half2_rn(v0, v1);
                }
            }
        }
    }
}

// ---------------- silu-mul ----------------
__global__ void silumul_k(const __half* __restrict__ gu, __half* __restrict__ out, int W)
{
    long r = blockIdx.x;
    const __half2* gp = reinterpret_cast<const __half2*>(gu + r*(long)(2*W));
    const __half2* up = reinterpret_cast<const __half2*>(gu + r*(long)(2*W) + W);
    __half2* op = reinterpret_cast<__half2*>(out + r*(long)W);
    for (int j = threadIdx.x; j < W/2; j += blockDim.x) {
        float2 gf = __half22float2(gp[j]);
        float2 uf = __half22float2(up[j]);
        op[j] = __floats2half2_rn(gf.x / (1.f + expf(-gf.x)) * uf.x,
                                  gf.y / (1.f + expf(-gf.y)) * uf.y);
    }
}

// ---------------- router (+ fused shared-expert gate + expert counting) ----------------
__global__ void router_k(const float* __restrict__ x2, const float* __restrict__ Wr,
                         const float* __restrict__ Wshg,
                         int* __restrict__ topi, float* __restrict__ topw,
                         float* __restrict__ sig, int* __restrict__ cnt)
{
    int t = blockIdx.x;
    __shared__ float xs[HID];
    __shared__ float pr[NEXP];
    __shared__ float sred[4];
    for (int i = threadIdx.x; i < HID; i += blockDim.x) xs[i] = x2[(long)t*HID + i];
    __syncthreads();
    float sdot = 0.f;
    for (int i = threadIdx.x; i < HID; i += blockDim.x) sdot += xs[i] * Wshg[i];
    for (int o = 16; o > 0; o >>= 1) sdot += __shfl_xor_sync(0xffffffffu, sdot, o);
    if ((threadIdx.x & 31) == 0) sred[threadIdx.x >> 5] = sdot;
    if (threadIdx.x < NEXP) {
        int e = threadIdx.x;
        float d = 0.f;
        for (int i = 0; i < HID; i++) d += xs[i] * Wr[i*NEXP + e];
        pr[e] = d;
    }
    __syncthreads();
    if (threadIdx.x == 0) {
        sig[t] = 1.f / (1.f + expf(-(sred[0]+sred[1]+sred[2]+sred[3])));
        float mx = -1e30f;
        for (int e = 0; e < NEXP; e++) mx = fmaxf(mx, pr[e]);
        float p[NEXP]; float sm2 = 0.f;
        for (int e = 0; e < NEXP; e++) { p[e] = expf(pr[e]-mx); sm2 += p[e]; }
        for (int e = 0; e < NEXP; e++) p[e] /= sm2;
        float tw = 0.f;
        int   idx[TOPK]; float val[TOPK];
        for (int kk = 0; kk < TOPK; kk++) {
            int bi = 0; float bv = -1.f;
            for (int e = 0; e < NEXP; e++) if (p[e] > bv) { bv = p[e]; bi = e; }
            idx[kk] = bi; val[kk] = bv; p[bi] = -2.f; tw += bv;
        }
        for (int kk = 0; kk < TOPK; kk++) {
            topi[t*TOPK+kk] = idx[kk];
            topw[t*TOPK+kk] = val[kk] / tw;
            atomicAdd(&cnt[idx[kk]], 1);
        }
    }
}

// ---------------- routing build ----------------
__global__ void zero32_k(int* cnt) { if (threadIdx.x < NEXP) cnt[threadIdx.x] = 0; }
__global__ void scan_k(const int* __restrict__ cnt, int* __restrict__ off, int* __restrict__ cur)
{
    if (threadIdx.x == 0) {
        int a = 0;
        for (int e = 0; e < NEXP; e++) { off[e] = a; cur[e] = a; a += cnt[e]; }
        off[NEXP] = a;
    }
}
__global__ void fill_k(const int* __restrict__ topi, int* __restrict__ cur,
                       int* __restrict__ ptok, int* __restrict__ ppos)
{
    int i = blockIdx.x*256 + threadIdx.x;
    if (i < NPAIR) {
        int e = topi[i];
        int p = atomicAdd(&cur[e], 1);
        ptok[p] = i / TOPK;
        ppos[i] = p;
    }
}

// ---------------- MoE reduction (fp16 down, half2 vectorized) ----------------
__global__ void moe_reduce_k(const __half* __restrict__ down, const int* __restrict__ ppos,
                             const float* __restrict__ topw, const float* __restrict__ h,
                             float* __restrict__ out)
{
    int t = blockIdx.x;
    long pos[TOPK]; float w[TOPK];
#pragma unroll
    for (int kk = 0; kk < TOPK; kk++) { pos[kk] = ppos[t*TOPK+kk]; w[kk] = topw[t*TOPK+kk]; }
    const float2* hp = reinterpret_cast<const float2*>(h + (long)t*HID);
    float2* op = reinterpret_cast<float2*>(out + (long)t*HID);
    for (int c = threadIdx.x; c < HID/2; c += blockDim.x) {
        float2 s = hp[c];
#pragma unroll
        for (int kk = 0; kk < TOPK; kk++) {
            float2 d = __half22float2(*reinterpret_cast<const __half2*>(&down[pos[kk]*HID + 2*c]));
            s.x += d.x * w[kk];
            s.y += d.y * w[kk];
        }
        op[c] = s;
    }
}

// ---------------- host launch ----------------
extern "C" void kernel_launch(void* const* d_in, const int* in_sizes, int n_in,
                              void* d_out, int out_size)
{
    (void)in_sizes; (void)out_size;
    if (n_in < 17) return;
    const float* hidden = (const float*)d_in[0];
    const float* ln1    = (const float*)d_in[1];
    const float* ln2    = (const float*)d_in[2];
    const float* qnw    = (const float*)d_in[3];
    const float* knw    = (const float*)d_in[4];
    const float* Wq     = (const float*)d_in[5];
    const float* Wk     = (const float*)d_in[6];
    const float* Wv     = (const float*)d_in[7];
    const float* Wo     = (const float*)d_in[8];
    const float* Wr     = (const float*)d_in[9];
    const float* Weg    = (const float*)d_in[10];
    const float* Weu    = (const float*)d_in[11];
    const float* Wed    = (const float*)d_in[12];
    const float* Wsg    = (const float*)d_in[13];
    const float* Wsu    = (const float*)d_in[14];
    const float* Wsd    = (const float*)d_in[15];
    const float* Wshg   = (const float*)d_in[16];
    float* out = (float*)d_out;

    float *xn, *hb, *cosT, *sinT, *topw, *sig;
    int *topi, *cnt, *off, *cur, *ptok, *ppos;
    __half *qkvh, *xh, *atth, *guh, *acth, *downh, *gsh, *shh;
    __half *WqkvT, *WoT, *WguT, *WedT, *WsguT, *WsdT;
    cudaGetSymbolAddress((void**)&xn,    g_xn);
    cudaGetSymbolAddress((void**)&hb,    g_h);
    cudaGetSymbolAddress((void**)&cosT,  g_cos);
    cudaGetSymbolAddress((void**)&sinT,  g_sin);
    cudaGetSymbolAddress((void**)&topi,  g_topi);
    cudaGetSymbolAddress((void**)&topw,  g_topw);
    cudaGetSymbolAddress((void**)&cnt,   g_cnt);
    cudaGetSymbolAddress((void**)&off,   g_off);
    cudaGetSymbolAddress((void**)&cur,   g_cur);
    cudaGetSymbolAddress((void**)&ptok,  g_ptok);
    cudaGetSymbolAddress((void**)&ppos,  g_ppos);
    cudaGetSymbolAddress((void**)&sig,   g_sig);
    cudaGetSymbolAddress((void**)&qkvh,  g_qkvh);
    cudaGetSymbolAddress((void**)&xh,    g_xh);
    cudaGetSymbolAddress((void**)&atth,  g_atth);
    cudaGetSymbolAddress((void**)&guh,   g_guh);
    cudaGetSymbolAddress((void**)&acth,  g_acth);
    cudaGetSymbolAddress((void**)&downh, g_downh);
    cudaGetSymbolAddress((void**)&gsh,   g_gsh);
    cudaGetSymbolAddress((void**)&shh,   g_shh);
    cudaGetSymbolAddress((void**)&WqkvT, g_Wqkv);
    cudaGetSymbolAddress((void**)&WoT,   g_WoT);
    cudaGetSymbolAddress((void**)&WguT,  g_WguT);
    cudaGetSymbolAddress((void**)&WedT,  g_WedT);
    cudaGetSymbolAddress((void**)&WsguT, g_WsguT);
    cudaGetSymbolAddress((void**)&WsdT,  g_WsdT);

    cudaFuncSetAttribute(flash_h_k, cudaFuncAttributeMaxDynamicSharedMemorySize, FLASHH_SMEM_BYTES);
    cudaFuncSetAttribute(mmh_k<1,false,false>, cudaFuncAttributeMaxDynamicSharedMemorySize, MMH_SMEM_BYTES);
    cudaFuncSetAttribute(mmh_k<3,false,false>, cudaFuncAttributeMaxDynamicSharedMemorySize, MMH_SMEM_BYTES);
    cudaFuncSetAttribute(mmh_k<4,false,false>, cudaFuncAttributeMaxDynamicSharedMemorySize, MMH_SMEM_BYTES);
    cudaFuncSetAttribute(mmh_k<4,true,true>,   cudaFuncAttributeMaxDynamicSharedMemorySize, MMH_SMEM_BYTES);
    cudaFuncSetAttribute(mmh_k<4,false,true>,  cudaFuncAttributeMaxDynamicSharedMemorySize, MMH_SMEM_BYTES);

    dim3 tb(32, 8);
    // --- weight transpose+fp16 conversion (once per launch) ---
    tcvt_k<<<dim3(4096/32, 2048/64), tb>>>(Wq, WqkvT, HID, 4096, 0, 0);
    tcvt_k<<<dim3( 512/32, 2048/64), tb>>>(Wk, WqkvT + (long)4096*HID, HID, 512, 0, 0);
    tcvt_k<<<dim3( 512/32, 2048/64), tb>>>(Wv, WqkvT + (long)4608*HID, HID, 512, 0, 0);
    tcvt_k<<<dim3(2048/32, 4096/64), tb>>>(Wo, WoT, 4096, 2048, 0, 0);
    tcvt_k<<<dim3(EI/32, HID/64, NEXP), tb>>>(Weg, WguT,                HID, EI, (long)HID*EI, (long)2*EI*HID);
    tcvt_k<<<dim3(EI/32, HID/64, NEXP), tb>>>(Weu, WguT + (long)EI*HID, HID, EI, (long)HID*EI, (long)2*EI*HID);
    tcvt_k<<<dim3(HID/32, EI/64, NEXP), tb>>>(Wed, WedT, EI, HID, (long)EI*HID, (long)EI*HID);
    tcvt_k<<<dim3(SI/32, HID/64), tb>>>(Wsg, WsguT,                HID, SI, 0, 0);
    tcvt_k<<<dim3(SI/32, HID/64), tb>>>(Wsu, WsguT + (long)SI*HID, HID, SI, 0, 0);
    tcvt_k<<<dim3(HID/32, SI/64), tb>>>(Wsd, WsdT, SI, HID, 0, 0);

    // --- attention block ---
    rmsnorm_k<<<T_TOK, 256>>>(hidden, ln1, xn, xh);

    mmh_k<4,false,false><<<dim3(QKVN/128, 32), 256, MMH_SMEM_BYTES>>>(
        T_TOK, QKVN, HID, xh, HID, WqkvT, 0, nullptr, qkvh, QKVN, nullptr, nullptr, nullptr);

    rope_tab_k<<<SEQ, HDIM/2>>>(cosT, sinT);
    qknr_k<<<T_TOK*(NHEAD+NKVH), HDIM>>>(qkvh, qnw, knw, cosT, sinT);

    flash_h_k<<<dim3(SEQ/64, NHEAD, BATCH), 128, FLASHH_SMEM_BYTES>>>(qkvh, atth);

    // h = hidden + att @ Wo
    mmh_k<1,false,false><<<dim3(16, 32), 256, MMH_SMEM_BYTES>>>(
        T_TOK, HID, NHEAD*HDIM, atth, NHEAD*HDIM, WoT, 0, hb, nullptr, HID, nullptr, nullptr, hidden);

    // --- MoE block ---
    rmsnorm_k<<<T_TOK, 256>>>(hb, ln2, xn, xh);

    zero32_k<<<1, 32>>>(cnt);
    router_k<<<T_TOK, 128>>>(xn, Wr, Wshg, topi, topw, sig, cnt);
    scan_k<<<1, 32>>>(cnt, off, cur);
    fill_k<<<(NPAIR+255)/256, 256>>>(topi, cur, ptok, ppos);

    // experts: merged gate|up -> guh; silu-mul -> acth; down -> downh
    mmh_k<4,true,true><<<dim3(2*EI/128, 32, NEXP), 256, MMH_SMEM_BYTES>>>(
        0, 2*EI, HID, xh, HID, WguT, (long)2*EI*HID, nullptr, guh, 2*EI, off, ptok, nullptr);
    silumul_k<<<NPAIR, 256>>>(guh, acth, EI);
    mmh_k<4,false,true><<<dim3(HID/128, 32, NEXP), 256, MMH_SMEM_BYTES>>>(
        0, HID, EI, acth, EI, WedT, (long)HID*EI, nullptr, downh, HID, off, nullptr, nullptr);

    moe_reduce_k<<<T_TOK, 256>>>(downh, ppos, topw, hb, out);

    // --- shared expert: merged gate|up -> gsh; silu-mul -> shh; down (rowscale-add) ---
    mmh_k<4,false,false><<<dim3(2*SI/128, 32), 256, MMH_SMEM_BYTES>>>(
        T_TOK, 2*SI, HID, xh, HID, WsguT, 0, nullptr, gsh, 2*SI, nullptr, nullptr, nullptr);
    silumul_k<<<T_TOK, 256>>>(gsh, shh, SI);
    mmh_k<3,false,false><<<dim3(HID/128, 32), 256, MMH_SMEM_BYTES>>>(
        T_TOK, HID, SI, shh, SI, WsdT, 0, out, nullptr, HID, nullptr, nullptr, sig);
}

// round 17
// speedup vs baseline: 1.1776x; 1.0170x over previous
#include <cuda_runtime.h>
#include <cuda_fp16.h>
#include <math.h>
#include <stdint.h>

// ---------------- problem constants ----------------
#define T_TOK 4096
#define HID   2048
#define SEQ   1024
#define BATCH 4
#define NHEAD 32
#define NKVH  4
#define HDIM  128
#define NEXP  32
#define TOPK  8
#define EI    768
#define SI    4096
#define GQA   8
#define EPSV  1e-6f
#define QKVN  (NHEAD*HDIM + 2*NKVH*HDIM)   // 5120
#define NPAIR (T_TOK*TOPK)

// ---------------- scratch (fp32) ----------------
__device__ float g_xn  [T_TOK*HID];
__device__ float g_h   [T_TOK*HID];
__device__ float g_cos[SEQ*(HDIM/2)];
__device__ float g_sin[SEQ*(HDIM/2)];
__device__ int   g_topi[NPAIR];
__device__ float g_topw[NPAIR];
__device__ int   g_cnt[NEXP];
__device__ int   g_off[NEXP+1];
__device__ int   g_cur[NEXP];
__device__ int   g_ptok[NPAIR];
__device__ int   g_ppos[NPAIR];
__device__ float g_sig[T_TOK];
// ---------------- scratch (fp16) ----------------
__device__ __half g_qkvh [(long)T_TOK*QKVN];
__device__ __half g_xh   [T_TOK*HID];
__device__ __half g_atth [T_TOK*NHEAD*HDIM];
__device__ __half g_acth [(long)NPAIR*EI];
__device__ __half g_downh[(long)NPAIR*HID];
__device__ __half g_shh  [T_TOK*SI];
// fp16 transposed weights [N][K]  (gate|up interleaved: row 2j = gate_j, 2j+1 = up_j)
__device__ __half g_Wqkv[QKVN*HID];
__device__ __half g_WoT [HID*NHEAD*HDIM];
__device__ __half g_WguT[(long)NEXP*2*EI*HID];
__device__ __half g_WedT[(long)NEXP*HID*EI];
__device__ __half g_WsguT[(long)2*SI*HID];
__device__ __half g_WsdT[HID*SI];

// ---------------- helpers ----------------
__device__ __forceinline__ uint32_t smem_u32(const void* p){
    uint32_t a;
    asm("{ .reg .u64 t; cvta.to.shared.u64 t, %1; cvt.u32.u64 %0, t; }" : "=r"(a) : "l"(p));
    return a;
}
__device__ __forceinline__ void cp_async16(uint32_t saddr, const void* gaddr, uint32_t sz){
    asm volatile("cp.async.cg.shared.global [%0], [%1], 16, %2;"
        :: "r"(saddr), "l"(gaddr), "r"(sz) : "memory");
}
__device__ __forceinline__ void cp_commit(){
    asm volatile("cp.async.commit_group;" ::: "memory");
}
template<int N>
__device__ __forceinline__ void cp_wait(){
    asm volatile("cp.async.wait_group %0;" :: "n"(N) : "memory");
}
__device__ __forceinline__ void mma_f16(float* c, uint32_t a0, uint32_t a1, uint32_t a2, uint32_t a3,
                                        uint32_t b0, uint32_t b1)
{
    asm volatile("mma.sync.aligned.m16n8k16.row.col.f32.f16.f16.f32 "
        "{%0,%1,%2,%3}, {%4,%5,%6,%7}, {%8,%9}, {%0,%1,%2,%3};"
        : "+f"(c[0]), "+f"(c[1]), "+f"(c[2]), "+f"(c[3])
        : "r"(a0), "r"(a1), "r"(a2), "r"(a3), "r"(b0), "r"(b1));
}
#define LDSM_X4(r0, r1, r2, r3, addr) \
    asm volatile("ldmatrix.sync.aligned.m8n8.x4.shared.b16 {%0,%1,%2,%3}, [%4];" \
        : "=r"(r0), "=r"(r1), "=r"(r2), "=r"(r3) : "r"(addr))
#define LDSM_X4_T(r0, r1, r2, r3, addr) \
    asm volatile("ldmatrix.sync.aligned.m8n8.x4.trans.shared.b16 {%0,%1,%2,%3}, [%4];" \
        : "=r"(r0), "=r"(r1), "=r"(r2), "=r"(r3) : "r"(addr))
__device__ __forceinline__ uint32_t packh2(float a, float b){
    __half2 h = __floats2half2_rn(a, b);
    return *reinterpret_cast<uint32_t*>(&h);
}

// ---------------- weight transpose + fp16 convert: src[K][N] -> dst rows (n*rowMul+rowOff) ----------------
__global__ void tcvt_k(const float* __restrict__ src, __half* __restrict__ dst, int K, int N,
                       long srcZ, long dstZ, int rowMul, int rowOff)
{
    __shared__ float t[64][33];
    long z = blockIdx.z;
    src += z * srcZ;
    dst += z * dstZ;
    int n0 = blockIdx.x*32, k0 = blockIdx.y*64;
    int tx = threadIdx.x, ty = threadIdx.y;
#pragma unroll
    for (int i = 0; i < 8; i++)
        t[ty + i*8][tx] = src[(long)(k0 + ty + i*8)*N + n0 + tx];
    __syncthreads();
#pragma unroll
    for (int i = 0; i < 4; i++) {
        int n = ty + i*8;
        __half2 h = __floats2half2_rn(t[2*tx][n], t[2*tx+1][n]);
        long row = (long)(n0+n)*rowMul + rowOff;
        *reinterpret_cast<__half2*>(&dst[row*K + k0 + 2*tx]) = h;
    }
}

// ---------------- rmsnorm over HID (writes fp32 + fp16) ----------------
__global__ void rmsnorm_k(const float* __restrict__ x, const float* __restrict__ w,
                          float* __restrict__ y, __half* __restrict__ yh)
{
    int row = blockIdx.x;
    const float* xr = x + (long)row*HID;
    float ss = 0.f;
    for (int i = threadIdx.x; i < HID; i += blockDim.x) { float v = xr[i]; ss += v*v; }
    __shared__ float red[32];
    for (int o = 16; o > 0; o >>= 1) ss += __shfl_xor_sync(0xffffffffu, ss, o);
    int warp = threadIdx.x >> 5, lane = threadIdx.x & 31;
    if (lane == 0) red[warp] = ss;
    __syncthreads();
    if (warp == 0) {
        ss = (lane < (blockDim.x >> 5)) ? red[lane] : 0.f;
        for (int o = 16; o > 0; o >>= 1) ss += __shfl_xor_sync(0xffffffffu, ss, o);
        if (lane == 0) red[0] = ss;
    }
    __syncthreads();
    float r = rsqrtf(red[0] / (float)HID + EPSV);
    for (int i = threadIdx.x; i < HID; i += blockDim.x) {
        float v = xr[i] * r * w[i];
        y [(long)row*HID + i] = v;
        yh[(long)row*HID + i] = __float2half(v);
    }
}

// ---------------- rope tables ----------------
__global__ void rope_tab_k(float* __restrict__ cosT, float* __restrict__ sinT)
{
    int s = blockIdx.x;
    int i = threadIdx.x;
    float inv = expf(-((float)(2*i) / (float)HDIM) * logf(1000000.0f));
    float ang = (float)s * inv;
    cosT[s*(HDIM/2)+i] = cosf(ang);
    sinT[s*(HDIM/2)+i] = sinf(ang);
}

// ---------------- per-head rmsnorm + rope, fp16 in-place; q+k heads in one grid ----------------
__global__ void qknr_k(__half* __restrict__ qkv,
                       const float* __restrict__ qnw, const float* __restrict__ knw,
                       const float* __restrict__ cosT, const float* __restrict__ sinT)
{
    long bh = blockIdx.x;
    int t = (int)(bh / (NHEAD + NKVH));
    int hh = (int)(bh % (NHEAD + NKVH));
    const float* nw = (hh < NHEAD) ? qnw : knw;
    int s = t & (SEQ-1);
    int d = threadIdx.x;
    __half* xp = qkv + (long)t*QKVN + hh*HDIM;
    float v = __half2float(xp[d]);
    float ss = v*v;
    for (int o = 16; o > 0; o >>= 1) ss += __shfl_xor_sync(0xffffffffu, ss, o);
    __shared__ float red[4];
    if ((threadIdx.x & 31) == 0) red[threadIdx.x >> 5] = ss;
    __syncthreads();
    float tot = red[0]+red[1]+red[2]+red[3];
    float r = rsqrtf(tot / (float)HDIM + EPSV);
    float xn = v * r * nw[d];
    __shared__ float xsh[HDIM];
    xsh[d] = xn;
    __syncthreads();
    float c, sn, oth;
    if (d < HDIM/2) { c = cosT[s*(HDIM/2)+d];          sn = sinT[s*(HDIM/2)+d];          oth = -xsh[d+HDIM/2]; }
    else            { c = cosT[s*(HDIM/2)+d-HDIM/2];   sn = sinT[s*(HDIM/2)+d-HDIM/2];   oth =  xsh[d-HDIM/2]; }
    xp[d] = __float2half(xn*c + oth*sn);
}

// ---------------- fp16 tensor-core flash attention (packed fp16 qkv input) ----------------
#define KPITCH 136
#define VPITCH 136
#define PPITCH 72
#define FLASHH_SMEM_BYTES ((64*KPITCH + 64*VPITCH + 64*PPITCH)*2)

__global__ void __launch_bounds__(128)
flash_h_k(const __half* __restrict__ qkv, __half* __restrict__ og)
{
    extern __shared__ __half fsh[];
    uint32_t sb = smem_u32(fsh);
    uint32_t KsU = sb;
    uint32_t VsU = sb + (uint32_t)(64*KPITCH)*2;
    uint32_t PsU = VsU + (uint32_t)(64*VPITCH)*2;
    __half* Ps = fsh + 64*KPITCH + 64*VPITCH;

    int qt = blockIdx.x, h = blockIdx.y, b = blockIdx.z;
    int kvh = h / GQA;
    int qs0 = qt*64;
    int tid = threadIdx.x, w = tid >> 5, lane = tid & 31;
    int g = lane >> 2, tg = lane & 3;
    float scale = rsqrtf((float)HDIM);

    uint32_t qa[8][4];
    {
        const __half* q0 = qkv + (long)(b*SEQ + qs0 + w*16 + g)*QKVN + h*HDIM;
        const __half* q8 = q0 + 8L*QKVN;
#pragma unroll
        for (int ks = 0; ks < 8; ks++) {
            int kb = ks*16;
            qa[ks][0] = packh2(__half2float(q0[kb+2*tg])*scale,   __half2float(q0[kb+2*tg+1])*scale);
            qa[ks][1] = packh2(__half2float(q8[kb+2*tg])*scale,   __half2float(q8[kb+2*tg+1])*scale);
            qa[ks][2] = packh2(__half2float(q0[kb+8+2*tg])*scale, __half2float(q0[kb+8+2*tg+1])*scale);
            qa[ks][3] = packh2(__half2float(q8[kb+8+2*tg])*scale, __half2float(q8[kb+8+2*tg+1])*scale);
        }
    }

    float m0 = -1e30f, m1 = -1e30f, l0 = 0.f, l1 = 0.f;
    float oac[16][4];
#pragma unroll
    for (int nt = 0; nt < 16; nt++)
#pragma unroll
        for (int r = 0; r < 4; r++) oac[nt][r] = 0.f;

    long kbase = (long)(b*SEQ)*QKVN + NHEAD*HDIM + kvh*HDIM;
    long vbase = kbase + (long)NKVH*HDIM;
    int pr0 = (w*16+g)*PPITCH, pr1 = (w*16+g+8)*PPITCH;

    uint32_t kFrag = KsU + (uint32_t)(((((lane>>4)<<3) + (lane&7))*KPITCH + ((lane>>3)&1)*8)*2);
    uint32_t pFrag = PsU + (uint32_t)(((w*16 + (lane&15))*PPITCH + ((lane>>4)&1)*8)*2);
    uint32_t vFrag = VsU + (uint32_t)(((lane&15)*VPITCH + ((lane>>4)<<3))*2);

    for (int jt = 0; jt <= qt; jt++) {
        __syncthreads();
        {
            const __half* kr = qkv + kbase + (long)(jt*64)*QKVN;
#pragma unroll
            for (int i = 0; i < 8; i++) {
                int idx = i*128 + tid;
                int r = idx >> 4, c = idx & 15;
                cp_async16(KsU + (uint32_t)(r*KPITCH + c*8)*2, kr + (long)r*QKVN + c*8, 16);
            }
            cp_commit();
            const __half* vr = qkv + vbase + (long)(jt*64)*QKVN;
#pragma unroll
            for (int i = 0; i < 8; i++) {
                int idx = i*128 + tid;
                int r = idx >> 4, c = idx & 15;
                cp_async16(VsU + (uint32_t)(r*VPITCH + c*8)*2, vr + (long)r*QKVN + c*8, 16);
            }
            cp_commit();
        }
        cp_wait<1>(); __syncthreads();

        float sacc[8][4];
#pragma unroll
        for (int nt = 0; nt < 8; nt++)
#pragma unroll
            for (int r = 0; r < 4; r++) sacc[nt][r] = 0.f;
#pragma unroll
        for (int ks = 0; ks < 8; ks++) {
#pragma unroll
            for (int ng = 0; ng < 4; ng++) {
                uint32_t r0, r1, r2, r3;
                LDSM_X4(r0, r1, r2, r3, kFrag + (uint32_t)(ng*16*KPITCH)*2 + ks*32);
                mma_f16(sacc[ng*2],   qa[ks][0], qa[ks][1], qa[ks][2], qa[ks][3], r0, r1);
                mma_f16(sacc[ng*2+1], qa[ks][0], qa[ks][1], qa[ks][2], qa[ks][3], r2, r3);
            }
        }
        int row0 = qs0 + w*16 + g, row1 = row0 + 8;
        if (jt == qt) {
            int cb = jt*64;
#pragma unroll
            for (int nt = 0; nt < 8; nt++) {
                int c0 = cb + nt*8 + 2*tg;
                if (c0   > row0) sacc[nt][0] = -1e30f;
                if (c0+1 > row0) sacc[nt][1] = -1e30f;
                if (c0   > row1) sacc[nt][2] = -1e30f;
                if (c0+1 > row1) sacc[nt][3] = -1e30f;
            }
        }
        float mx0 = m0, mx1 = m1;
#pragma unroll
        for (int nt = 0; nt < 8; nt++) {
            mx0 = fmaxf(mx0, fmaxf(sacc[nt][0], sacc[nt][1]));
            mx1 = fmaxf(mx1, fmaxf(sacc[nt][2], sacc[nt][3]));
        }
        mx0 = fmaxf(mx0, __shfl_xor_sync(0xffffffffu, mx0, 1));
        mx0 = fmaxf(mx0, __shfl_xor_sync(0xffffffffu, mx0, 2));
        mx1 = fmaxf(mx1, __shfl_xor_sync(0xffffffffu, mx1, 1));
        mx1 = fmaxf(mx1, __shfl_xor_sync(0xffffffffu, mx1, 2));
        float c0 = expf(m0 - mx0), c1 = expf(m1 - mx1);
        float s0 = 0.f, s1 = 0.f;
#pragma unroll
        for (int nt = 0; nt < 8; nt++) {
            sacc[nt][0] = expf(sacc[nt][0] - mx0);
            sacc[nt][1] = expf(sacc[nt][1] - mx0);
            sacc[nt][2] = expf(sacc[nt][2] - mx1);
            sacc[nt][3] = expf(sacc[nt][3] - mx1);
            s0 += sacc[nt][0] + sacc[nt][1];
            s1 += sacc[nt][2] + sacc[nt][3];
        }
        s0 += __shfl_xor_sync(0xffffffffu, s0, 1);
        s0 += __shfl_xor_sync(0xffffffffu, s0, 2);
        s1 += __shfl_xor_sync(0xffffffffu, s1, 1);
        s1 += __shfl_xor_sync(0xffffffffu, s1, 2);
        l0 = l0*c0 + s0;  l1 = l1*c1 + s1;  m0 = mx0;  m1 = mx1;
#pragma unroll
        for (int nt = 0; nt < 16; nt++) {
            oac[nt][0] *= c0; oac[nt][1] *= c0;
            oac[nt][2] *= c1; oac[nt][3] *= c1;
        }
#pragma unroll
        for (int nt = 0; nt < 8; nt++) {
            int pc = nt*8 + 2*tg;
            *reinterpret_cast<__half2*>(Ps + pr0 + pc) = __floats2half2_rn(sacc[nt][0], sacc[nt][1]);
            *reinterpret_cast<__half2*>(Ps + pr1 + pc) = __floats2half2_rn(sacc[nt][2], sacc[nt][3]);
        }
        cp_wait<0>(); __syncthreads();

#pragma unroll
        for (int ks = 0; ks < 4; ks++) {
            uint32_t a0, a1, a2, a3;
            LDSM_X4(a0, a1, a2, a3, pFrag + ks*32);
#pragma unroll
            for (int ng = 0; ng < 8; ng++) {
                uint32_t r0, r1, r2, r3;
                LDSM_X4_T(r0, r1, r2, r3, vFrag + (uint32_t)(ks*16*VPITCH)*2 + ng*32);
                mma_f16(oac[ng*2],   a0, a1, a2, a3, r0, r1);
                mma_f16(oac[ng*2+1], a0, a1, a2, a3, r2, r3);
            }
        }
    }

    float i0 = 1.f/l0, i1 = 1.f/l1;
    long o0 = ((long)(b*SEQ + qs0 + w*16 + g)*NHEAD + h)*HDIM;
    long o8 = o0 + 8L*NHEAD*HDIM;
#pragma unroll
    for (int nt = 0; nt < 16; nt++) {
        int c = nt*8 + 2*tg;
        *reinterpret_cast<__half2*>(&og[o0+c]) = __floats2half2_rn(oac[nt][0]*i0, oac[nt][1]*i0);
        *reinterpret_cast<__half2*>(&og[o8+c]) = __floats2half2_rn(oac[nt][2]*i1, oac[nt][3]*i1);
    }
}

// ---------------- fp16 mma GEMM: 128x128x32, 256 thr (2x4 warps, 64x32 tiles), ldmatrix, 4-stage ----------------
// C[M,N] = A[M,K] @ B^T, B stored [N][K] fp16.
// EPI: 1=resid add(extra), 3=C += acc*extra[row], 4=Ch = half(acc),
//      5=Ch[col/2] = half(silu(v0)*v1)   (gate|up interleaved; ldc = output width)
#define HPITCH 40
#define TBUF_H (128*HPITCH)
#define STAGE_B (2*TBUF_H*2)
#define NSTAGE 4
#define MMH_SMEM_BYTES (NSTAGE*STAGE_B)

template<int EPI, bool AIDX, bool EXPERT>
__global__ void __launch_bounds__(256, 2)
mmh_k(int M, int N, int Kd,
      const __half* __restrict__ A, int lda,
      const __half* __restrict__ B, long strideB,
      float* __restrict__ C, __half* __restrict__ Ch, int ldc,
      const int* __restrict__ offs, const int* __restrict__ aidx,
      const float* __restrict__ extra)
{
    extern __shared__ __align__(16) char smh[];
    uint32_t sb = smem_u32(smh);

    int rbase = 0, mrows = M;
    const __half* Bp = B;
    if (EXPERT) {
        int e = blockIdx.z;
        rbase = offs[e];
        mrows = offs[e+1] - rbase;
        Bp = B + (long)e * strideB;
    }
    int bm0 = blockIdx.y * 128;
    if (bm0 >= mrows) return;
    int bn0 = blockIdx.x * 128;

    int tid = threadIdx.x, lane = tid & 31, wid = tid >> 5;
    int g = lane >> 2, tg = lane & 3;
    int warp_m = wid & 1, warp_n = wid >> 1;

    const char* aptr;
    uint32_t aok;
    {
        int lr = bm0 + (tid >> 1);
        if (lr < mrows) {
            long gr = AIDX ? (long)aidx[rbase + lr] : (long)(rbase + lr);
            aptr = (const char*)(A + gr*(long)lda + (tid & 1)*16);
            aok = 16;
        } else { aptr = (const char*)A; aok = 0; }
    }
    const char* bptr = (const char*)(Bp + (long)(bn0 + (tid >> 1))*Kd + (tid & 1)*16);
    uint32_t aoff = (uint32_t)((tid >> 1)*HPITCH + (tid & 1)*16)*2;
    uint32_t boff = (uint32_t)(TBUF_H + (tid >> 1)*HPITCH + (tid & 1)*16)*2;

    uint32_t aFragB = (uint32_t)((warp_m*64 + (lane & 15))*HPITCH + ((lane >> 4) & 1)*8)*2;
    uint32_t bFragB = (uint32_t)(TBUF_H + (warp_n*32 + ((lane >> 4) << 3) + (lane & 7))*HPITCH
                                 + ((lane >> 3) & 1)*8)*2;

    float acc[4][4][4];
#pragma unroll
    for (int mt = 0; mt < 4; mt++)
#pragma unroll
        for (int nt = 0; nt < 4; nt++)
#pragma unroll
            for (int r = 0; r < 4; r++) acc[mt][nt][r] = 0.f;

    int nc = Kd >> 5;

    // prologue: stage chunks 0,1,2
#pragma unroll
    for (int pc = 0; pc < 3; pc++) {
        if (pc < nc) {
            uint32_t s0 = sb + pc*STAGE_B;
            long kadv = (long)pc*64;
            cp_async16(s0 + aoff,      aptr + kadv,      aok);
            cp_async16(s0 + aoff + 16, aptr + kadv + 16, aok);
            cp_async16(s0 + boff,      bptr + kadv,      16);
            cp_async16(s0 + boff + 16, bptr + kadv + 16, 16);
        }
        cp_commit();
    }

    for (int c = 0; c < nc; c++) {
        int p = c % NSTAGE;
        cp_wait<2>();
        __syncthreads();
        if (c + 3 < nc) {
            int q = (c + 3) % NSTAGE;
            uint32_t s0 = sb + q*STAGE_B;
            long kadv = (long)(c + 3)*64;
            cp_async16(s0 + aoff,      aptr + kadv,      aok);
            cp_async16(s0 + aoff + 16, aptr + kadv + 16, aok);
            cp_async16(s0 + boff,      bptr + kadv,      16);
            cp_async16(s0 + boff + 16, bptr + kadv + 16, 16);
        }
        cp_commit();

        uint32_t aB = sb + p*STAGE_B + aFragB;
        uint32_t bB = sb + p*STAGE_B + bFragB;
#pragma unroll
        for (int ks = 0; ks < 2; ks++) {
            uint32_t a[4][4];
#pragma unroll
            for (int mt = 0; mt < 4; mt++)
                LDSM_X4(a[mt][0], a[mt][1], a[mt][2], a[mt][3],
                        aB + (uint32_t)(mt*16*HPITCH)*2 + ks*32);
            uint32_t bq[2][4];
#pragma unroll
            for (int ntp = 0; ntp < 2; ntp++)
                LDSM_X4(bq[ntp][0], bq[ntp][1], bq[ntp][2], bq[ntp][3],
                        bB + (uint32_t)(ntp*16*HPITCH)*2 + ks*32);
#pragma unroll
            for (int mt = 0; mt < 4; mt++)
#pragma unroll
                for (int nt = 0; nt < 4; nt++)
                    mma_f16(acc[mt][nt], a[mt][0], a[mt][1], a[mt][2], a[mt][3],
                            bq[nt >> 1][(nt & 1)*2], bq[nt >> 1][(nt & 1)*2 + 1]);
        }
    }

#pragma unroll
    for (int mt = 0; mt < 4; mt++) {
#pragma unroll
        for (int nt = 0; nt < 4; nt++) {
            int col = bn0 + warp_n*32 + nt*8 + 2*tg;
#pragma unroll
            for (int half = 0; half < 2; half++) {
                int lr = warp_m*64 + mt*16 + g + half*8;
                int grow = bm0 + lr;
                if (grow >= mrows) continue;
                long cr = rbase + grow;
                float v0 = acc[mt][nt][half*2+0];
                float v1 = acc[mt][nt][half*2+1];
                if (EPI == 1) {
                    long o0 = cr*(long)ldc + col;
                    C[o0]   = extra[o0]   + v0;
                    C[o0+1] = extra[o0+1] + v1;
                } else if (EPI == 3) {
                    long o0 = cr*(long)ldc + col;
                    float s = extra[grow];
                    C[o0]   += v0 * s;
                    C[o0+1] += v1 * s;
                } else if (EPI == 4) {
                    long o0 = cr*(long)ldc + col;
                    *reinterpret_cast<__half2*>(&Ch[o0]) = __floats2half2_rn(v0, v1);
                } else if (EPI == 5) {
                    // interleaved gate|up: v0 = gate, v1 = up for output column col/2
                    Ch[cr*(long)ldc + (col >> 1)] =
                        __float2half(v0 / (1.f + expf(-v0)) * v1);
                }
            }
        }
    }
}

// ---------------- router (+ fused shared-expert gate + expert counting) ----------------
__global__ void router_k(const float* __restrict__ x2, const float* __restrict__ Wr,
                         const float* __restrict__ Wshg,
                         int* __restrict__ topi, float* __restrict__ topw,
                         float* __restrict__ sig, int* __restrict__ cnt)
{
    int t = blockIdx.x;
    __shared__ float xs[HID];
    __shared__ float pr[NEXP];
    __shared__ float sred[4];
    for (int i = threadIdx.x; i < HID; i += blockDim.x) xs[i] = x2[(long)t*HID + i];
    __syncthreads();
    float sdot = 0.f;
    for (int i = threadIdx.x; i < HID; i += blockDim.x) sdot += xs[i] * Wshg[i];
    for (int o = 16; o > 0; o >>= 1) sdot += __shfl_xor_sync(0xffffffffu, sdot, o);
    if ((threadIdx.x & 31) == 0) sred[threadIdx.x >> 5] = sdot;
    if (threadIdx.x < NEXP) {
        int e = threadIdx.x;
        float d = 0.f;
        for (int i = 0; i < HID; i++) d += xs[i] * Wr[i*NEXP + e];
        pr[e] = d;
    }
    __syncthreads();
    if (threadIdx.x == 0) {
        sig[t] = 1.f / (1.f + expf(-(sred[0]+sred[1]+sred[2]+sred[3])));
        float mx = -1e30f;
        for (int e = 0; e < NEXP; e++) mx = fmaxf(mx, pr[e]);
        float p[NEXP]; float sm2 = 0.f;
        for (int e = 0; e < NEXP; e++) { p[e] = expf(pr[e]-mx); sm2 += p[e]; }
        for (int e = 0; e < NEXP; e++) p[e] /= sm2;
        float tw = 0.f;
        int   idx[TOPK]; float val[TOPK];
        for (int kk = 0; kk < TOPK; kk++) {
            int bi = 0; float bv = -1.f;
            for (int e = 0; e < NEXP; e++) if (p[e] > bv) { bv = p[e]; bi = e; }
            idx[kk] = bi; val[kk] = bv; p[bi] = -2.f; tw += bv;
        }
        for (int kk = 0; kk < TOPK; kk++) {
            topi[t*TOPK+kk] = idx[kk];
            topw[t*TOPK+kk] = val[kk] / tw;
            atomicAdd(&cnt[idx[kk]], 1);
        }
    }
}

// ---------------- routing build ----------------
__global__ void zero32_k(int* cnt) { if (threadIdx.x < NEXP) cnt[threadIdx.x] = 0; }
__global__ void scan_k(const int* __restrict__ cnt, int* __restrict__ off, int* __restrict__ cur)
{
    if (threadIdx.x == 0) {
        int a = 0;
        for (int e = 0; e < NEXP; e++) { off[e] = a; cur[e] = a; a += cnt[e]; }
        off[NEXP] = a;
    }
}
__global__ void fill_k(const int* __restrict__ topi, int* __restrict__ cur,
                       int* __restrict__ ptok, int* __restrict__ ppos)
{
    int i = blockIdx.x*256 + threadIdx.x;
    if (i < NPAIR) {
        int e = topi[i];
        int p = atomicAdd(&cur[e], 1);
        ptok[p] = i / TOPK;
        ppos[i] = p;
    }
}

// ---------------- MoE reduction (fp16 down, half2 vectorized) ----------------
__global__ void moe_reduce_k(const __half* __restrict__ down, const int* __restrict__ ppos,
                             const float* __restrict__ topw, const float* __restrict__ h,
                             float* __restrict__ out)
{
    int t = blockIdx.x;
    long pos[TOPK]; float w[TOPK];
#pragma unroll
    for (int kk = 0; kk < TOPK; kk++) { pos[kk] = ppos[t*TOPK+kk]; w[kk] = topw[t*TOPK+kk]; }
    const float2* hp = reinterpret_cast<const float2*>(h + (long)t*HID);
    float2* op = reinterpret_cast<float2*>(out + (long)t*HID);
    for (int c = threadIdx.x; c < HID/2; c += blockDim.x) {
        float2 s = hp[c];
#pragma unroll
        for (int kk = 0; kk < TOPK; kk++) {
            float2 d = __half22float2(*reinterpret_cast<const __half2*>(&down[pos[kk]*HID + 2*c]));
            s.x += d.x * w[kk];
            s.y += d.y * w[kk];
        }
        op[c] = s;
    }
}

// ---------------- host launch ----------------
extern "C" void kernel_launch(void* const* d_in, const int* in_sizes, int n_in,
                              void* d_out, int out_size)
{
    (void)in_sizes; (void)out_size;
    if (n_in < 17) return;
    const float* hidden = (const float*)d_in[0];
    const float* ln1    = (const float*)d_in[1];
    const float* ln2    = (const float*)d_in[2];
    const float* qnw    = (const float*)d_in[3];
    const float* knw    = (const float*)d_in[4];
    const float* Wq     = (const float*)d_in[5];
    const float* Wk     = (const float*)d_in[6];
    const float* Wv     = (const float*)d_in[7];
    const float* Wo     = (const float*)d_in[8];
    const float* Wr     = (const float*)d_in[9];
    const float* Weg    = (const float*)d_in[10];
    const float* Weu    = (const float*)d_in[11];
    const float* Wed    = (const float*)d_in[12];
    const float* Wsg    = (const float*)d_in[13];
    const float* Wsu    = (const float*)d_in[14];
    const float* Wsd    = (const float*)d_in[15];
    const float* Wshg   = (const float*)d_in[16];
    float* out = (float*)d_out;

    float *xn, *hb, *cosT, *sinT, *topw, *sig;
    int *topi, *cnt, *off, *cur, *ptok, *ppos;
    __half *qkvh, *xh, *atth, *acth, *downh, *shh;
    __half *WqkvT, *WoT, *WguT, *WedT, *WsguT, *WsdT;
    cudaGetSymbolAddress((void**)&xn,    g_xn);
    cudaGetSymbolAddress((void**)&hb,    g_h);
    cudaGetSymbolAddress((void**)&cosT,  g_cos);
    cudaGetSymbolAddress((void**)&sinT,  g_sin);
    cudaGetSymbolAddress((void**)&topi,  g_topi);
    cudaGetSymbolAddress((void**)&topw,  g_topw);
    cudaGetSymbolAddress((void**)&cnt,   g_cnt);
    cudaGetSymbolAddress((void**)&off,   g_off);
    cudaGetSymbolAddress((void**)&cur,   g_cur);
    cudaGetSymbolAddress((void**)&ptok,  g_ptok);
    cudaGetSymbolAddress((void**)&ppos,  g_ppos);
    cudaGetSymbolAddress((void**)&sig,   g_sig);
    cudaGetSymbolAddress((void**)&qkvh,  g_qkvh);
    cudaGetSymbolAddress((void**)&xh,    g_xh);
    cudaGetSymbolAddress((void**)&atth,  g_atth);
    cudaGetSymbolAddress((void**)&acth,  g_acth);
    cudaGetSymbolAddress((void**)&downh, g_downh);
    cudaGetSymbolAddress((void**)&shh,   g_shh);
    cudaGetSymbolAddress((void**)&WqkvT, g_Wqkv);
    cudaGetSymbolAddress((void**)&WoT,   g_WoT);
    cudaGetSymbolAddress((void**)&WguT,  g_WguT);
    cudaGetSymbolAddress((void**)&WedT,  g_WedT);
    cudaGetSymbolAddress((void**)&WsguT, g_WsguT);
    cudaGetSymbolAddress((void**)&WsdT,  g_WsdT);

    cudaFuncSetAttribute(flash_h_k, cudaFuncAttributeMaxDynamicSharedMemorySize, FLASHH_SMEM_BYTES);
    cudaFuncSetAttribute(mmh_k<1,false,false>, cudaFuncAttributeMaxDynamicSharedMemorySize, MMH_SMEM_BYTES);
    cudaFuncSetAttribute(mmh_k<3,false,false>, cudaFuncAttributeMaxDynamicSharedMemorySize, MMH_SMEM_BYTES);
    cudaFuncSetAttribute(mmh_k<4,false,false>, cudaFuncAttributeMaxDynamicSharedMemorySize, MMH_SMEM_BYTES);
    cudaFuncSetAttribute(mmh_k<5,true,true>,   cudaFuncAttributeMaxDynamicSharedMemorySize, MMH_SMEM_BYTES);
    cudaFuncSetAttribute(mmh_k<5,false,false>, cudaFuncAttributeMaxDynamicSharedMemorySize, MMH_SMEM_BYTES);
    cudaFuncSetAttribute(mmh_k<4,false,true>,  cudaFuncAttributeMaxDynamicSharedMemorySize, MMH_SMEM_BYTES);

    dim3 tb(32, 8);
    // --- weight transpose+fp16 conversion (once per launch) ---
    tcvt_k<<<dim3(4096/32, 2048/64), tb>>>(Wq, WqkvT, HID, 4096, 0, 0, 1, 0);
    tcvt_k<<<dim3( 512/32, 2048/64), tb>>>(Wk, WqkvT + (long)4096*HID, HID, 512, 0, 0, 1, 0);
    tcvt_k<<<dim3( 512/32, 2048/64), tb>>>(Wv, WqkvT + (long)4608*HID, HID, 512, 0, 0, 1, 0);
    tcvt_k<<<dim3(2048/32, 4096/64), tb>>>(Wo, WoT, 4096, 2048, 0, 0, 1, 0);
    // experts: interleave gate/up rows (merged row 2j = gate_j, 2j+1 = up_j)
    tcvt_k<<<dim3(EI/32, HID/64, NEXP), tb>>>(Weg, WguT, HID, EI, (long)HID*EI, (long)2*EI*HID, 2, 0);
    tcvt_k<<<dim3(EI/32, HID/64, NEXP), tb>>>(Weu, WguT, HID, EI, (long)HID*EI, (long)2*EI*HID, 2, 1);
    tcvt_k<<<dim3(HID/32, EI/64, NEXP), tb>>>(Wed, WedT, EI, HID, (long)EI*HID, (long)EI*HID, 1, 0);
    // shared expert: interleaved gate/up
    tcvt_k<<<dim3(SI/32, HID/64), tb>>>(Wsg, WsguT, HID, SI, 0, 0, 2, 0);
    tcvt_k<<<dim3(SI/32, HID/64), tb>>>(Wsu, WsguT, HID, SI, 0, 0, 2, 1);
    tcvt_k<<<dim3(HID/32, SI/64), tb>>>(Wsd, WsdT, SI, HID, 0, 0, 1, 0);

    // --- attention block ---
    rmsnorm_k<<<T_TOK, 256>>>(hidden, ln1, xn, xh);

    mmh_k<4,false,false><<<dim3(QKVN/128, 32), 256, MMH_SMEM_BYTES>>>(
        T_TOK, QKVN, HID, xh, HID, WqkvT, 0, nullptr, qkvh, QKVN, nullptr, nullptr, nullptr);

    rope_tab_k<<<SEQ, HDIM/2>>>(cosT, sinT);
    qknr_k<<<T_TOK*(NHEAD+NKVH), HDIM>>>(qkvh, qnw, knw, cosT, sinT);

    flash_h_k<<<dim3(SEQ/64, NHEAD, BATCH), 128, FLASHH_SMEM_BYTES>>>(qkvh, atth);

    // h = hidden + att @ Wo
    mmh_k<1,false,false><<<dim3(16, 32), 256, MMH_SMEM_BYTES>>>(
        T_TOK, HID, NHEAD*HDIM, atth, NHEAD*HDIM, WoT, 0, hb, nullptr, HID, nullptr, nullptr, hidden);

    // --- MoE block ---
    rmsnorm_k<<<T_TOK, 256>>>(hb, ln2, xn, xh);

    zero32_k<<<1, 32>>>(cnt);
    router_k<<<T_TOK, 128>>>(xn, Wr, Wshg, topi, topw, sig, cnt);
    scan_k<<<1, 32>>>(cnt, off, cur);
    fill_k<<<(NPAIR+255)/256, 256>>>(topi, cur, ptok, ppos);

    // experts: fused gate|up+silu -> acth; down -> downh
    mmh_k<5,true,true><<<dim3(2*EI/128, 32, NEXP), 256, MMH_SMEM_BYTES>>>(
        0, 2*EI, HID, xh, HID, WguT, (long)2*EI*HID, nullptr, acth, EI, off, ptok, nullptr);
    mmh_k<4,false,true><<<dim3(HID/128, 32, NEXP), 256, MMH_SMEM_BYTES>>>(
        0, HID, EI, acth, EI, WedT, (long)HID*EI, nullptr, downh, HID, off, nullptr, nullptr);

    moe_reduce_k<<<T_TOK, 256>>>(downh, ppos, topw, hb, out);

    // --- shared expert: fused gate|up+silu -> shh; down (rowscale-add) ---
    mmh_k<5,false,false><<<dim3(2*SI/128, 32), 256, MMH_SMEM_BYTES>>>(
        T_TOK, 2*SI, HID, xh, HID, WsguT, 0, nullptr, shh, SI, nullptr, nullptr, nullptr);
    mmh_k<3,false,false><<<dim3(HID/128, 32), 256, MMH_SMEM_BYTES>>>(
        T_TOK, HID, SI, shh, SI, WsdT, 0, out, nullptr, HID, nullptr, nullptr, sig);
}